// round 11
// baseline (speedup 1.0000x reference)
#include <cuda_runtime.h>
#include <cuda_fp16.h>
#include <math_constants.h>
#include <cstdint>

#define BATCH 4
#define SEQ   2048
#define DIM   1024
#define DIM3  3072
#define NEGV  (-1e20f)

// ---------------- scratch (device globals; no allocation) ----------------
__device__ float g_qkv   [(size_t)BATCH * SEQ * DIM3];
__device__ float g_scores[(size_t)BATCH * SEQ * SEQ];

__device__ __half g_xh  [(size_t)BATCH * SEQ * DIM];
__device__ __half g_qkvh[(size_t)BATCH * SEQ * DIM3];
__device__ __half g_qkvl[(size_t)BATCH * SEQ * DIM3];
__device__ __half g_wqh [(size_t)DIM3 * DIM];
__device__ __half g_wql [(size_t)DIM3 * DIM];
__device__ __half g_vth [(size_t)BATCH * DIM * SEQ];
__device__ __half g_vtl [(size_t)BATCH * DIM * SEQ];
__device__ __half g_sh  [(size_t)BATCH * SEQ * SEQ];
__device__ __half g_ch  [(size_t)BATCH * SEQ * DIM];
__device__ __half g_woh [(size_t)DIM * DIM];
__device__ __half g_wol [(size_t)DIM * DIM];

// ---------------- helpers ----------------
__device__ __forceinline__ uint32_t smem_u32(const void* p) {
    uint32_t a;
    asm("{ .reg .u64 t; cvta.to.shared.u64 t, %1; cvt.u32.u64 %0, t; }" : "=r"(a) : "l"(p));
    return a;
}
__device__ __forceinline__ uint32_t sw128(uint32_t o) { return o ^ ((o >> 3) & 0x70); }

#define CP_ASYNC16(dst, src) \
    asm volatile("cp.async.cg.shared.global [%0], [%1], 16;" :: "r"(dst), "l"(src))

#define MBARRIER_INIT(addr, cnt) \
    asm volatile("mbarrier.init.shared.b64 [%0], %1;" :: "r"(addr), "r"(cnt) : "memory")
#define MBARRIER_ARRIVE(addr) \
    asm volatile("mbarrier.arrive.shared.b64 _, [%0];" :: "r"(addr) : "memory")
// .noinc is load-bearing: default form pre-increments pending count (net zero -> deadlock).
#define CPASYNC_MBAR_ARRIVE_NOINC(addr) \
    asm volatile("cp.async.mbarrier.arrive.noinc.shared.b64 [%0];" :: "r"(addr) : "memory")
#define MBARRIER_WAIT_PARITY(addr, par) do { \
    uint32_t _m = (addr), _p = (par), _d; \
    asm volatile("{\n\t.reg .pred p;\n\tmbarrier.try_wait.parity.acquire.cta.shared::cta.b64 p, [%1], %2;\n\tselp.b32 %0, 1, 0, p;\n\t}" \
        : "=r"(_d) : "r"(_m), "r"(_p) : "memory"); \
    if (!_d) { \
        asm volatile("{\n\t.reg .pred P1;\n\tWL_%=:\n\tmbarrier.try_wait.parity.acquire.cta.shared::cta.b64 P1, [%0], %1, 0x989680;\n\t@P1 bra.uni WD_%=;\n\tbra.uni WL_%=;\n\tWD_%=:\n\t}" \
            :: "r"(_m), "r"(_p) : "memory"); \
    } } while (0)

#define LDSM4(r0, r1, r2, r3, a) \
    asm volatile("ldmatrix.sync.aligned.m8n8.x4.shared.b16 {%0,%1,%2,%3}, [%4];" \
        : "=r"(r0), "=r"(r1), "=r"(r2), "=r"(r3) : "r"(a))

#define MMA16816F(c, a, b) \
    asm volatile("mma.sync.aligned.m16n8k16.row.col.f32.f16.f16.f32 " \
        "{%0,%1,%2,%3}, {%4,%5,%6,%7}, {%8,%9}, {%0,%1,%2,%3};" \
        : "+f"((c)[0]), "+f"((c)[1]), "+f"((c)[2]), "+f"((c)[3]) \
        : "r"((a)[0]), "r"((a)[1]), "r"((a)[2]), "r"((a)[3]), "r"((b)[0]), "r"((b)[1]))

#define MMA16816H(c, a, b) \
    asm volatile("mma.sync.aligned.m16n8k16.row.col.f16.f16.f16.f16 " \
        "{%0,%1}, {%2,%3,%4,%5}, {%6,%7}, {%0,%1};" \
        : "+r"((c)[0]), "+r"((c)[1]) \
        : "r"((a)[0]), "r"((a)[1]), "r"((a)[2]), "r"((a)[3]), "r"((b)[0]), "r"((b)[1]))

// ---------------- GEMM: C[m,n] = sum_k A[m,k]*B[n,k] (K-major both) ----------------
// CTA tile 128x64, BK=64. 288 threads: 8 consumer warps (32x32 tiles) + 1 producer
// warp. 3-stage mbarrier ring; no __syncthreads in mainloop. 2 CTAs/SM.
#define OFF_A  0
#define OFF_BH 16384
#define OFF_BL 24576
#define STG    32768
#define SM_TILES 1024
#define GEMM_SMEM (SM_TILES + 3 * STG)   // 97.25 KB

__global__ __launch_bounds__(288, 2) void gemm_mma(
    const __half* __restrict__ Ah, long long sA, int lda,
    const __half* __restrict__ Bh, const __half* __restrict__ Bl, long long sB, int ldb,
    float* __restrict__ Cf, __half* __restrict__ Chi, __half* __restrict__ Clo,
    long long sC, int ldc,
    const float* __restrict__ bias,
    const int* __restrict__ mask, long long sM, float scale,
    int K)
{
    extern __shared__ char smem[];
    uint32_t sb = smem_u32(smem);
    int tid = threadIdx.x, w = tid >> 5, l = tid & 31;
    int b = blockIdx.z;
    Ah += (size_t)b * sA;
    Bh += (size_t)b * sB; Bl += (size_t)b * sB;
    if (Cf)  Cf  += (size_t)b * sC;
    if (Chi) Chi += (size_t)b * sC;
    if (Clo) Clo += (size_t)b * sC;
    if (mask) mask += (size_t)b * sM;
    int row0 = blockIdx.y * 128, col0 = blockIdx.x * 64;

    const __half* Ahr = Ah + (size_t)row0 * lda;
    const __half* Bhr = Bh + (size_t)col0 * ldb;
    const __half* Blr = Bl + (size_t)col0 * ldb;

    uint32_t FULL  = sb + 0;    // 3 x 8B
    uint32_t EMPTY = sb + 24;   // 3 x 8B
    if (tid == 0) {
#pragma unroll
        for (int s = 0; s < 3; s++) {
            MBARRIER_INIT(FULL + s * 8, 32);    // producer warp threads (noinc arrives)
            MBARRIER_INIT(EMPTY + s * 8, 256);  // consumer threads
        }
    }
    __syncthreads();

    const int L = K >> 6;

    if (w == 8) {
        // -------- producer warp --------
        for (int j = 0; j < L; j++) {
            int s = j % 3, r = j / 3;
            if (j >= 3) MBARRIER_WAIT_PARITY(EMPTY + s * 8, (uint32_t)((r - 1) & 1));
            uint32_t base = sb + SM_TILES + s * STG;
            int k0 = j * 64;
#pragma unroll 4
            for (int t = 0; t < 64; t++) {
                int idx = t * 32 + l;
                uint32_t dst; const __half* src;
                if (idx < 1024) {                         // A: 128 rows x 8 chunks
                    int row = idx >> 3, ch = idx & 7;
                    dst = base + OFF_A + sw128((uint32_t)row * 128 + ch * 16);
                    src = Ahr + (size_t)row * lda + k0 + ch * 8;
                } else if (idx < 1536) {                  // B hi: 64 rows x 8
                    int i2 = idx - 1024;
                    int row = i2 >> 3, ch = i2 & 7;
                    dst = base + OFF_BH + sw128((uint32_t)row * 128 + ch * 16);
                    src = Bhr + (size_t)row * ldb + k0 + ch * 8;
                } else {                                  // B lo: 64 rows x 8
                    int i2 = idx - 1536;
                    int row = i2 >> 3, ch = i2 & 7;
                    dst = base + OFF_BL + sw128((uint32_t)row * 128 + ch * 16);
                    src = Blr + (size_t)row * ldb + k0 + ch * 8;
                }
                CP_ASYNC16(dst, src);
            }
            CPASYNC_MBAR_ARRIVE_NOINC(FULL + s * 8);
        }
        asm volatile("cp.async.commit_group;\ncp.async.wait_group 0;" ::: "memory");
        return;
    }

    // -------- consumer warps (w = 0..7) --------
    int wm = (w >> 1) * 32, wn = (w & 1) * 32;

    uint32_t aoffb[2], boffb[2];
#pragma unroll
    for (int mt = 0; mt < 2; mt++)
        aoffb[mt] = sw128((uint32_t)(wm + mt * 16 + (l & 15)) * 128 + (l >> 4) * 16);
#pragma unroll
    for (int g = 0; g < 2; g++)
        boffb[g] = sw128((uint32_t)(wn + g * 16 + (l & 15)) * 128 + (l >> 4) * 16);

    float acc[2][4][4];
    uint32_t acc16[2][4][2];
#pragma unroll
    for (int mt = 0; mt < 2; mt++)
#pragma unroll
        for (int nt = 0; nt < 4; nt++) {
#pragma unroll
            for (int r = 0; r < 4; r++) acc[mt][nt][r] = 0.0f;
            acc16[mt][nt][0] = 0u; acc16[mt][nt][1] = 0u;
        }

    for (int j = 0; j < L; j++) {
        int s = j % 3, r = j / 3;
        MBARRIER_WAIT_PARITY(FULL + s * 8, (uint32_t)(r & 1));
        uint32_t base = sb + SM_TILES + s * STG;
#pragma unroll
        for (int ks = 0; ks < 4; ks++) {
            uint32_t kx = (uint32_t)ks * 32;
            uint32_t a[2][4], bb[4][2];
#pragma unroll
            for (int mt = 0; mt < 2; mt++)
                LDSM4(a[mt][0], a[mt][1], a[mt][2], a[mt][3], base + OFF_A + (aoffb[mt] ^ kx));
#pragma unroll
            for (int g = 0; g < 2; g++) {
                uint32_t q0, q1, q2, q3;
                LDSM4(q0, q1, q2, q3, base + OFF_BH + (boffb[g] ^ kx));
                bb[2 * g][0] = q0; bb[2 * g][1] = q2;
                bb[2 * g + 1][0] = q1; bb[2 * g + 1][1] = q3;
            }
#pragma unroll
            for (int mt = 0; mt < 2; mt++)
#pragma unroll
                for (int nt = 0; nt < 4; nt++)
                    MMA16816F(acc[mt][nt], a[mt], bb[nt]);
            // reload B-lo into the same fragment registers (in-order issue: safe WAR)
#pragma unroll
            for (int g = 0; g < 2; g++) {
                uint32_t q0, q1, q2, q3;
                LDSM4(q0, q1, q2, q3, base + OFF_BL + (boffb[g] ^ kx));
                bb[2 * g][0] = q0; bb[2 * g][1] = q2;
                bb[2 * g + 1][0] = q1; bb[2 * g + 1][1] = q3;
            }
#pragma unroll
            for (int mt = 0; mt < 2; mt++)
#pragma unroll
                for (int nt = 0; nt < 4; nt++)
                    MMA16816H(acc16[mt][nt], a[mt], bb[nt]);
        }
        MBARRIER_ARRIVE(EMPTY + s * 8);
    }

    // ---- epilogue ----
#pragma unroll
    for (int mt = 0; mt < 2; mt++) {
        int r0 = row0 + wm + mt * 16 + (l >> 2);
        int r1 = r0 + 8;
#pragma unroll
        for (int nt = 0; nt < 4; nt++) {
            float2 f01 = __half22float2(*(__half2*)&acc16[mt][nt][0]);
            float2 f23 = __half22float2(*(__half2*)&acc16[mt][nt][1]);
            float2 v0 = make_float2(acc[mt][nt][0] + f01.x, acc[mt][nt][1] + f01.y);
            float2 v1 = make_float2(acc[mt][nt][2] + f23.x, acc[mt][nt][3] + f23.y);

            int c = col0 + wn + nt * 8 + 2 * (l & 3);
            if (bias) {
                float2 bb2 = *(const float2*)(bias + c);
                v0.x += bb2.x; v0.y += bb2.y; v1.x += bb2.x; v1.y += bb2.y;
            }
            if (mask) {
                int2 m0 = *(const int2*)(mask + (size_t)r0 * ldc + c);
                int2 m1 = *(const int2*)(mask + (size_t)r1 * ldc + c);
                v0.x = m0.x ? NEGV : v0.x * scale;
                v0.y = m0.y ? NEGV : v0.y * scale;
                v1.x = m1.x ? NEGV : v1.x * scale;
                v1.y = m1.y ? NEGV : v1.y * scale;
            }
            if (Cf) {
                *(float2*)(Cf + (size_t)r0 * ldc + c) = v0;
                *(float2*)(Cf + (size_t)r1 * ldc + c) = v1;
            }
            if (Chi) {
                __half h0 = __float2half(v0.x), h1 = __float2half(v0.y);
                __half h2 = __float2half(v1.x), h3 = __float2half(v1.y);
                *(__half2*)(Chi + (size_t)r0 * ldc + c) = __halves2half2(h0, h1);
                *(__half2*)(Chi + (size_t)r1 * ldc + c) = __halves2half2(h2, h3);
                if (Clo) {
                    __half l0 = __float2half(v0.x - __half2float(h0));
                    __half l1 = __float2half(v0.y - __half2float(h1));
                    __half l2 = __float2half(v1.x - __half2float(h2));
                    __half l3 = __float2half(v1.y - __half2float(h3));
                    *(__half2*)(Clo + (size_t)r0 * ldc + c) = __halves2half2(l0, l1);
                    *(__half2*)(Clo + (size_t)r1 * ldc + c) = __halves2half2(l2, l3);
                }
            }
        }
    }
}

// ---------------- conversions ----------------
__global__ __launch_bounds__(256) void split_hi(
    const float4* __restrict__ in, __half* __restrict__ oh, long long n4)
{
    long long i = (long long)blockIdx.x * blockDim.x + threadIdx.x;
    if (i >= n4) return;
    float4 x = in[i];
    __half2 h0 = __floats2half2_rn(x.x, x.y);
    __half2 h1 = __floats2half2_rn(x.z, x.w);
    *(uint2*)(oh + i * 4) = make_uint2(*(uint32_t*)&h0, *(uint32_t*)&h1);
}

__global__ __launch_bounds__(256) void splitT_kernel(
    const float* __restrict__ in, int ldin, long long sIn,
    __half* __restrict__ oh, __half* __restrict__ ol, int ldout, long long sOut)
{
    __shared__ float t[32][33];
    int b = blockIdx.z;
    in += (size_t)b * sIn; oh += (size_t)b * sOut; ol += (size_t)b * sOut;
    int c0 = blockIdx.x * 32, r0 = blockIdx.y * 32;
    int tx = threadIdx.x & 31, ty = threadIdx.x >> 5;
#pragma unroll
    for (int k = 0; k < 4; k++) {
        int r = r0 + ty + k * 8;
        t[ty + k * 8][tx] = in[(size_t)r * ldin + c0 + tx];
    }
    __syncthreads();
#pragma unroll
    for (int k = 0; k < 4; k++) {
        int c = c0 + ty + k * 8;
        float v = t[tx][ty + k * 8];
        __half h = __float2half(v);
        oh[(size_t)c * ldout + r0 + tx] = h;
        ol[(size_t)c * ldout + r0 + tx] = __float2half(v - __half2float(h));
    }
}

// ---------------- softmax: f32 scores -> fp16 attn ----------------
__global__ __launch_bounds__(256) void softmax_h(
    const float* __restrict__ sc, __half* __restrict__ sh, int n)
{
    __shared__ float buf[SEQ];
    __shared__ float red[256];
    const float* row = sc + (size_t)blockIdx.x * n;
    __half* oh = sh + (size_t)blockIdx.x * n;
    int tid = threadIdx.x;

    float m = -CUDART_INF_F;
    for (int i = tid; i < n; i += 256) { float x = row[i]; buf[i] = x; m = fmaxf(m, x); }
    red[tid] = m; __syncthreads();
    for (int s = 128; s > 0; s >>= 1) {
        if (tid < s) red[tid] = fmaxf(red[tid], red[tid + s]);
        __syncthreads();
    }
    m = red[0];
    __syncthreads();

    float sum = 0.0f;
    for (int i = tid; i < n; i += 256) {
        float e = __expf(buf[i] - m);
        buf[i] = e; sum += e;
    }
    red[tid] = sum; __syncthreads();
    for (int s = 128; s > 0; s >>= 1) {
        if (tid < s) red[tid] += red[tid + s];
        __syncthreads();
    }
    float inv = 1.0f / red[0];
    for (int i = tid; i < n; i += 256) oh[i] = __float2half(buf[i] * inv);
}

// ---------------- host ----------------
extern "C" void kernel_launch(void* const* d_in, const int* in_sizes, int n_in,
                              void* d_out, int out_size)
{
    const float* X     = (const float*)d_in[0];
    const int*   mask  = (const int*)d_in[1];
    const float* W_qkv = (const float*)d_in[2];
    const float* b_qkv = (const float*)d_in[3];
    const float* W_out = (const float*)d_in[4];
    const float* b_out = (const float*)d_in[5];
    float*       out   = (float*)d_out;

    float *qkv, *scores;
    __half *xh, *qkvh, *qkvl, *wqh, *wql, *vth, *vtl, *sh, *ch, *woh, *wol;
    cudaGetSymbolAddress((void**)&qkv, g_qkv);
    cudaGetSymbolAddress((void**)&scores, g_scores);
    cudaGetSymbolAddress((void**)&xh, g_xh);
    cudaGetSymbolAddress((void**)&qkvh, g_qkvh); cudaGetSymbolAddress((void**)&qkvl, g_qkvl);
    cudaGetSymbolAddress((void**)&wqh, g_wqh); cudaGetSymbolAddress((void**)&wql, g_wql);
    cudaGetSymbolAddress((void**)&vth, g_vth); cudaGetSymbolAddress((void**)&vtl, g_vtl);
    cudaGetSymbolAddress((void**)&sh, g_sh);
    cudaGetSymbolAddress((void**)&ch, g_ch);
    cudaGetSymbolAddress((void**)&woh, g_woh); cudaGetSymbolAddress((void**)&wol, g_wol);

    cudaFuncSetAttribute(gemm_mma, cudaFuncAttributeMaxDynamicSharedMemorySize, GEMM_SMEM);

    const int M = BATCH * SEQ;
    const float scale = 1.0f / 32.0f;

    {   // X -> hi fp16
        long long n4 = (long long)M * DIM / 4;
        split_hi<<<(unsigned)((n4 + 255) / 256), 256>>>((const float4*)X, xh, n4);
    }
    splitT_kernel<<<dim3(DIM3 / 32, DIM / 32, 1), 256>>>(W_qkv, DIM3, 0, wqh, wql, DIM, 0);
    splitT_kernel<<<dim3(DIM / 32, DIM / 32, 1), 256>>>(W_out, DIM, 0, woh, wol, DIM, 0);

    // 1) QKV = X @ Wqkv^T + b  -> f32 + fp16 hi/lo
    gemm_mma<<<dim3(DIM3 / 64, M / 128, 1), 288, GEMM_SMEM>>>(
        xh, 0, DIM, wqh, wql, 0, DIM,
        qkv, qkvh, qkvl, 0, DIM3, b_qkv, nullptr, 0, 1.0f, DIM);

    // V^T hi/lo
    splitT_kernel<<<dim3(DIM / 32, SEQ / 32, BATCH), 256>>>(
        qkv + 2 * DIM, DIM3, (long long)SEQ * DIM3, vth, vtl, SEQ, (long long)DIM * SEQ);

    // 2) scores = mask ? NEG : (Q K^T)/32  -> f32
    gemm_mma<<<dim3(SEQ / 64, SEQ / 128, BATCH), 288, GEMM_SMEM>>>(
        qkvh, (long long)SEQ * DIM3, DIM3,
        qkvh + DIM, qkvl + DIM, (long long)SEQ * DIM3, DIM3,
        scores, nullptr, nullptr, (long long)SEQ * SEQ, SEQ,
        nullptr, mask, (long long)SEQ * SEQ, scale, DIM);

    // 3) softmax f32 -> fp16
    softmax_h<<<BATCH * SEQ, 256>>>(scores, sh, SEQ);

    // 4) ctx = attn @ V  -> fp16 hi only
    gemm_mma<<<dim3(DIM / 64, SEQ / 128, BATCH), 288, GEMM_SMEM>>>(
        sh, (long long)SEQ * SEQ, SEQ,
        vth, vtl, (long long)DIM * SEQ, SEQ,
        nullptr, ch, nullptr, (long long)SEQ * DIM, DIM,
        nullptr, nullptr, 0, 1.0f, SEQ);

    // 5) out = ctx @ Wout^T + b
    gemm_mma<<<dim3(DIM / 64, M / 128, 1), 288, GEMM_SMEM>>>(
        ch, 0, DIM, woh, wol, 0, DIM,
        out, nullptr, nullptr, 0, DIM, b_out, nullptr, 0, 1.0f, DIM);
}

// round 12
// speedup vs baseline: 1.6157x; 1.6157x over previous
#include <cuda_runtime.h>
#include <cuda_fp16.h>
#include <math_constants.h>
#include <cstdint>

#define BATCH 4
#define SEQ   2048
#define DIM   1024
#define DIM3  3072
#define NEGV  (-1e20f)

// ---------------- scratch (device globals; no allocation) ----------------
__device__ float g_qkv   [(size_t)BATCH * SEQ * DIM3];
__device__ float g_scores[(size_t)BATCH * SEQ * SEQ];

__device__ __half g_xh  [(size_t)BATCH * SEQ * DIM];
__device__ __half g_qkvh[(size_t)BATCH * SEQ * DIM3];
__device__ __half g_qkvl[(size_t)BATCH * SEQ * DIM3];
__device__ __half g_wqh [(size_t)DIM3 * DIM];
__device__ __half g_wql [(size_t)DIM3 * DIM];
__device__ __half g_vth [(size_t)BATCH * DIM * SEQ];
__device__ __half g_vtl [(size_t)BATCH * DIM * SEQ];
__device__ __half g_sh  [(size_t)BATCH * SEQ * SEQ];
__device__ __half g_ch  [(size_t)BATCH * SEQ * DIM];
__device__ __half g_woh [(size_t)DIM * DIM];
__device__ __half g_wol [(size_t)DIM * DIM];

// ---------------- helpers ----------------
__device__ __forceinline__ uint32_t smem_u32(const void* p) {
    uint32_t a;
    asm("{ .reg .u64 t; cvta.to.shared.u64 t, %1; cvt.u32.u64 %0, t; }" : "=r"(a) : "l"(p));
    return a;
}
__device__ __forceinline__ uint32_t sw128(uint32_t o) { return o ^ ((o >> 3) & 0x70); }

#define CP_ASYNC16(dst, src) \
    asm volatile("cp.async.cg.shared.global [%0], [%1], 16;" :: "r"(dst), "l"(src))

#define MBARRIER_INIT(addr, cnt) \
    asm volatile("mbarrier.init.shared.b64 [%0], %1;" :: "r"(addr), "r"(cnt) : "memory")
#define MBARRIER_ARRIVE(addr) \
    asm volatile("mbarrier.arrive.shared.b64 _, [%0];" :: "r"(addr) : "memory")
// .noinc is load-bearing: default form pre-increments pending count (net zero -> deadlock).
#define CPASYNC_MBAR_ARRIVE_NOINC(addr) \
    asm volatile("cp.async.mbarrier.arrive.noinc.shared.b64 [%0];" :: "r"(addr) : "memory")
#define MBARRIER_WAIT_PARITY(addr, par) do { \
    uint32_t _m = (addr), _p = (par), _d; \
    asm volatile("{\n\t.reg .pred p;\n\tmbarrier.try_wait.parity.acquire.cta.shared::cta.b64 p, [%1], %2;\n\tselp.b32 %0, 1, 0, p;\n\t}" \
        : "=r"(_d) : "r"(_m), "r"(_p) : "memory"); \
    if (!_d) { \
        asm volatile("{\n\t.reg .pred P1;\n\tWL_%=:\n\tmbarrier.try_wait.parity.acquire.cta.shared::cta.b64 P1, [%0], %1, 0x989680;\n\t@P1 bra.uni WD_%=;\n\tbra.uni WL_%=;\n\tWD_%=:\n\t}" \
            :: "r"(_m), "r"(_p) : "memory"); \
    } } while (0)

#define LDSM4(r0, r1, r2, r3, a) \
    asm volatile("ldmatrix.sync.aligned.m8n8.x4.shared.b16 {%0,%1,%2,%3}, [%4];" \
        : "=r"(r0), "=r"(r1), "=r"(r2), "=r"(r3) : "r"(a))

#define MMA16816F(c, a, b) \
    asm volatile("mma.sync.aligned.m16n8k16.row.col.f32.f16.f16.f32 " \
        "{%0,%1,%2,%3}, {%4,%5,%6,%7}, {%8,%9}, {%0,%1,%2,%3};" \
        : "+f"((c)[0]), "+f"((c)[1]), "+f"((c)[2]), "+f"((c)[3]) \
        : "r"((a)[0]), "r"((a)[1]), "r"((a)[2]), "r"((a)[3]), "r"((b)[0]), "r"((b)[1]))

#define MMA16816H(c, a, b) \
    asm volatile("mma.sync.aligned.m16n8k16.row.col.f16.f16.f16.f16 " \
        "{%0,%1}, {%2,%3,%4,%5}, {%6,%7}, {%0,%1};" \
        : "+r"((c)[0]), "+r"((c)[1]) \
        : "r"((a)[0]), "r"((a)[1]), "r"((a)[2]), "r"((b)[0]), "r"((b)[1]), "r"((a)[3]))

// NOTE: careful - macro above must keep operand order. Rewritten correctly below.
#undef MMA16816H
#define MMA16816H(c, a, b) \
    asm volatile("mma.sync.aligned.m16n8k16.row.col.f16.f16.f16.f16 " \
        "{%0,%1}, {%2,%3,%4,%5}, {%6,%7}, {%0,%1};" \
        : "+r"((c)[0]), "+r"((c)[1]) \
        : "r"((a)[0]), "r"((a)[1]), "r"((a)[2]), "r"((a)[3]), "r"((b)[0]), "r"((b)[1]))

// ---------------- GEMM: C[m,n] = sum_k A[m,k]*B[n,k] (K-major both) ----------------
// CTA tile 128x64, BK=64, 256 threads (8 warps, 32x32 warp tiles), 2 CTAs/SM.
// 3-stage mbarrier ring, loads distributed over all threads, no __syncthreads
// in the mainloop (max warp drift ~1 chunk instead of hard convoy).
#define OFF_A  0
#define OFF_BH 16384
#define OFF_BL 24576
#define STG    32768
#define SM_TILES 1024
#define GEMM_SMEM (SM_TILES + 3 * STG)   // 97.25 KB

__device__ __forceinline__ void load_chunk(
    uint32_t base,
    const __half* __restrict__ Ahr, int lda,
    const __half* __restrict__ Bhr, const __half* __restrict__ Blr, int ldb,
    int k0, int tid)
{
#pragma unroll
    for (int it = 0; it < 4; it++) {           // A: 128 rows x 8 chunks
        int idx = tid + it * 256;
        int row = idx >> 3, ch = idx & 7;
        uint32_t d = sw128((uint32_t)row * 128 + ch * 16);
        CP_ASYNC16(base + OFF_A + d, Ahr + (size_t)row * lda + k0 + ch * 8);
    }
#pragma unroll
    for (int it = 0; it < 2; it++) {           // B hi/lo: 64 rows x 8 each
        int idx = tid + it * 256;
        int row = idx >> 3, ch = idx & 7;
        uint32_t d = sw128((uint32_t)row * 128 + ch * 16);
        size_t eb = (size_t)row * ldb + k0 + ch * 8;
        CP_ASYNC16(base + OFF_BH + d, Bhr + eb);
        CP_ASYNC16(base + OFF_BL + d, Blr + eb);
    }
}

__global__ __launch_bounds__(256, 2) void gemm_mma(
    const __half* __restrict__ Ah, long long sA, int lda,
    const __half* __restrict__ Bh, const __half* __restrict__ Bl, long long sB, int ldb,
    float* __restrict__ Cf, __half* __restrict__ Chi, __half* __restrict__ Clo,
    long long sC, int ldc,
    const float* __restrict__ bias,
    const int* __restrict__ mask, long long sM, float scale,
    int K)
{
    extern __shared__ char smem[];
    uint32_t sb = smem_u32(smem);
    int tid = threadIdx.x, w = tid >> 5, l = tid & 31;
    int b = blockIdx.z;
    Ah += (size_t)b * sA;
    Bh += (size_t)b * sB; Bl += (size_t)b * sB;
    if (Cf)  Cf  += (size_t)b * sC;
    if (Chi) Chi += (size_t)b * sC;
    if (Clo) Clo += (size_t)b * sC;
    if (mask) mask += (size_t)b * sM;
    int row0 = blockIdx.y * 128, col0 = blockIdx.x * 64;

    const __half* Ahr = Ah + (size_t)row0 * lda;
    const __half* Bhr = Bh + (size_t)col0 * ldb;
    const __half* Blr = Bl + (size_t)col0 * ldb;

    uint32_t FULL  = sb + 0;    // 3 x 8B
    uint32_t EMPTY = sb + 24;   // 3 x 8B
    if (tid == 0) {
#pragma unroll
        for (int s = 0; s < 3; s++) {
            MBARRIER_INIT(FULL + s * 8, 256);   // cp.async noinc arrivals (all threads)
            MBARRIER_INIT(EMPTY + s * 8, 8);    // one lane per warp
        }
    }
    __syncthreads();

    int wm = (w >> 1) * 32, wn = (w & 1) * 32;

    uint32_t aoffb[2], boffb[2];
#pragma unroll
    for (int mt = 0; mt < 2; mt++)
        aoffb[mt] = sw128((uint32_t)(wm + mt * 16 + (l & 15)) * 128 + (l >> 4) * 16);
#pragma unroll
    for (int g = 0; g < 2; g++)
        boffb[g] = sw128((uint32_t)(wn + g * 16 + (l & 15)) * 128 + (l >> 4) * 16);

    float acc[2][4][4];
    uint32_t acc16[2][4][2];
#pragma unroll
    for (int mt = 0; mt < 2; mt++)
#pragma unroll
        for (int nt = 0; nt < 4; nt++) {
#pragma unroll
            for (int r = 0; r < 4; r++) acc[mt][nt][r] = 0.0f;
            acc16[mt][nt][0] = 0u; acc16[mt][nt][1] = 0u;
        }

    const int L = K >> 6;
    // preamble: fill stages 0,1
    load_chunk(sb + SM_TILES + 0 * STG, Ahr, lda, Bhr, Blr, ldb, 0, tid);
    CPASYNC_MBAR_ARRIVE_NOINC(FULL + 0 * 8);
    load_chunk(sb + SM_TILES + 1 * STG, Ahr, lda, Bhr, Blr, ldb, 64, tid);
    CPASYNC_MBAR_ARRIVE_NOINC(FULL + 1 * 8);

    for (int j = 0; j < L; j++) {
        int s = j % 3;
        MBARRIER_WAIT_PARITY(FULL + s * 8, (uint32_t)((j / 3) & 1));

        if (j + 2 < L) {
            int sp = (j + 2) % 3;        // == (j-1)%3 for j>=1
            if (j >= 1)
                MBARRIER_WAIT_PARITY(EMPTY + sp * 8, (uint32_t)(((j - 1) / 3) & 1));
            load_chunk(sb + SM_TILES + sp * STG, Ahr, lda, Bhr, Blr, ldb, (j + 2) * 64, tid);
            CPASYNC_MBAR_ARRIVE_NOINC(FULL + sp * 8);
        }

        uint32_t base = sb + SM_TILES + s * STG;
#pragma unroll
        for (int ks = 0; ks < 4; ks++) {
            uint32_t kx = (uint32_t)ks * 32;
            uint32_t a[2][4], bb[4][2];
#pragma unroll
            for (int mt = 0; mt < 2; mt++)
                LDSM4(a[mt][0], a[mt][1], a[mt][2], a[mt][3], base + OFF_A + (aoffb[mt] ^ kx));
#pragma unroll
            for (int g = 0; g < 2; g++) {
                uint32_t q0, q1, q2, q3;
                LDSM4(q0, q1, q2, q3, base + OFF_BH + (boffb[g] ^ kx));
                bb[2 * g][0] = q0; bb[2 * g][1] = q2;
                bb[2 * g + 1][0] = q1; bb[2 * g + 1][1] = q3;
            }
#pragma unroll
            for (int mt = 0; mt < 2; mt++)
#pragma unroll
                for (int nt = 0; nt < 4; nt++)
                    MMA16816F(acc[mt][nt], a[mt], bb[nt]);
            // reload B-lo into same fragment regs (in-order issue: safe WAR)
#pragma unroll
            for (int g = 0; g < 2; g++) {
                uint32_t q0, q1, q2, q3;
                LDSM4(q0, q1, q2, q3, base + OFF_BL + (boffb[g] ^ kx));
                bb[2 * g][0] = q0; bb[2 * g][1] = q2;
                bb[2 * g + 1][0] = q1; bb[2 * g + 1][1] = q3;
            }
#pragma unroll
            for (int mt = 0; mt < 2; mt++)
#pragma unroll
                for (int nt = 0; nt < 4; nt++)
                    MMA16816H(acc16[mt][nt], a[mt], bb[nt]);
        }
        if (l == 0) MBARRIER_ARRIVE(EMPTY + s * 8);
    }

    // ---- epilogue ----
#pragma unroll
    for (int mt = 0; mt < 2; mt++) {
        int r0 = row0 + wm + mt * 16 + (l >> 2);
        int r1 = r0 + 8;
#pragma unroll
        for (int nt = 0; nt < 4; nt++) {
            float2 f01 = __half22float2(*(__half2*)&acc16[mt][nt][0]);
            float2 f23 = __half22float2(*(__half2*)&acc16[mt][nt][1]);
            float2 v0 = make_float2(acc[mt][nt][0] + f01.x, acc[mt][nt][1] + f01.y);
            float2 v1 = make_float2(acc[mt][nt][2] + f23.x, acc[mt][nt][3] + f23.y);

            int c = col0 + wn + nt * 8 + 2 * (l & 3);
            if (bias) {
                float2 bb2 = *(const float2*)(bias + c);
                v0.x += bb2.x; v0.y += bb2.y; v1.x += bb2.x; v1.y += bb2.y;
            }
            if (mask) {
                int2 m0 = *(const int2*)(mask + (size_t)r0 * ldc + c);
                int2 m1 = *(const int2*)(mask + (size_t)r1 * ldc + c);
                v0.x = m0.x ? NEGV : v0.x * scale;
                v0.y = m0.y ? NEGV : v0.y * scale;
                v1.x = m1.x ? NEGV : v1.x * scale;
                v1.y = m1.y ? NEGV : v1.y * scale;
            }
            if (Cf) {
                *(float2*)(Cf + (size_t)r0 * ldc + c) = v0;
                *(float2*)(Cf + (size_t)r1 * ldc + c) = v1;
            }
            if (Chi) {
                __half h0 = __float2half(v0.x), h1 = __float2half(v0.y);
                __half h2 = __float2half(v1.x), h3 = __float2half(v1.y);
                *(__half2*)(Chi + (size_t)r0 * ldc + c) = __halves2half2(h0, h1);
                *(__half2*)(Chi + (size_t)r1 * ldc + c) = __halves2half2(h2, h3);
                if (Clo) {
                    __half l0 = __float2half(v0.x - __half2float(h0));
                    __half l1 = __float2half(v0.y - __half2float(h1));
                    __half l2 = __float2half(v1.x - __half2float(h2));
                    __half l3 = __float2half(v1.y - __half2float(h3));
                    *(__half2*)(Clo + (size_t)r0 * ldc + c) = __halves2half2(l0, l1);
                    *(__half2*)(Clo + (size_t)r1 * ldc + c) = __halves2half2(l2, l3);
                }
            }
        }
    }
}

// ---------------- conversions ----------------
__global__ __launch_bounds__(256) void split_hi(
    const float4* __restrict__ in, __half* __restrict__ oh, long long n4)
{
    long long i = (long long)blockIdx.x * blockDim.x + threadIdx.x;
    if (i >= n4) return;
    float4 x = in[i];
    __half2 h0 = __floats2half2_rn(x.x, x.y);
    __half2 h1 = __floats2half2_rn(x.z, x.w);
    *(uint2*)(oh + i * 4) = make_uint2(*(uint32_t*)&h0, *(uint32_t*)&h1);
}

__global__ __launch_bounds__(256) void splitT_kernel(
    const float* __restrict__ in, int ldin, long long sIn,
    __half* __restrict__ oh, __half* __restrict__ ol, int ldout, long long sOut)
{
    __shared__ float t[32][33];
    int b = blockIdx.z;
    in += (size_t)b * sIn; oh += (size_t)b * sOut; ol += (size_t)b * sOut;
    int c0 = blockIdx.x * 32, r0 = blockIdx.y * 32;
    int tx = threadIdx.x & 31, ty = threadIdx.x >> 5;
#pragma unroll
    for (int k = 0; k < 4; k++) {
        int r = r0 + ty + k * 8;
        t[ty + k * 8][tx] = in[(size_t)r * ldin + c0 + tx];
    }
    __syncthreads();
#pragma unroll
    for (int k = 0; k < 4; k++) {
        int c = c0 + ty + k * 8;
        float v = t[tx][ty + k * 8];
        __half h = __float2half(v);
        oh[(size_t)c * ldout + r0 + tx] = h;
        ol[(size_t)c * ldout + r0 + tx] = __float2half(v - __half2float(h));
    }
}

// ---------------- softmax: f32 scores -> fp16 attn ----------------
__global__ __launch_bounds__(256) void softmax_h(
    const float* __restrict__ sc, __half* __restrict__ sh, int n)
{
    __shared__ float buf[SEQ];
    __shared__ float red[256];
    const float* row = sc + (size_t)blockIdx.x * n;
    __half* oh = sh + (size_t)blockIdx.x * n;
    int tid = threadIdx.x;

    float m = -CUDART_INF_F;
    for (int i = tid; i < n; i += 256) { float x = row[i]; buf[i] = x; m = fmaxf(m, x); }
    red[tid] = m; __syncthreads();
    for (int s = 128; s > 0; s >>= 1) {
        if (tid < s) red[tid] = fmaxf(red[tid], red[tid + s]);
        __syncthreads();
    }
    m = red[0];
    __syncthreads();

    float sum = 0.0f;
    for (int i = tid; i < n; i += 256) {
        float e = __expf(buf[i] - m);
        buf[i] = e; sum += e;
    }
    red[tid] = sum; __syncthreads();
    for (int s = 128; s > 0; s >>= 1) {
        if (tid < s) red[tid] += red[tid + s];
        __syncthreads();
    }
    float inv = 1.0f / red[0];
    for (int i = tid; i < n; i += 256) oh[i] = __float2half(buf[i] * inv);
}

// ---------------- host ----------------
extern "C" void kernel_launch(void* const* d_in, const int* in_sizes, int n_in,
                              void* d_out, int out_size)
{
    const float* X     = (const float*)d_in[0];
    const int*   mask  = (const int*)d_in[1];
    const float* W_qkv = (const float*)d_in[2];
    const float* b_qkv = (const float*)d_in[3];
    const float* W_out = (const float*)d_in[4];
    const float* b_out = (const float*)d_in[5];
    float*       out   = (float*)d_out;

    float *qkv, *scores;
    __half *xh, *qkvh, *qkvl, *wqh, *wql, *vth, *vtl, *sh, *ch, *woh, *wol;
    cudaGetSymbolAddress((void**)&qkv, g_qkv);
    cudaGetSymbolAddress((void**)&scores, g_scores);
    cudaGetSymbolAddress((void**)&xh, g_xh);
    cudaGetSymbolAddress((void**)&qkvh, g_qkvh); cudaGetSymbolAddress((void**)&qkvl, g_qkvl);
    cudaGetSymbolAddress((void**)&wqh, g_wqh); cudaGetSymbolAddress((void**)&wql, g_wql);
    cudaGetSymbolAddress((void**)&vth, g_vth); cudaGetSymbolAddress((void**)&vtl, g_vtl);
    cudaGetSymbolAddress((void**)&sh, g_sh);
    cudaGetSymbolAddress((void**)&ch, g_ch);
    cudaGetSymbolAddress((void**)&woh, g_woh); cudaGetSymbolAddress((void**)&wol, g_wol);

    cudaFuncSetAttribute(gemm_mma, cudaFuncAttributeMaxDynamicSharedMemorySize, GEMM_SMEM);

    const int M = BATCH * SEQ;
    const float scale = 1.0f / 32.0f;

    {   // X -> hi fp16
        long long n4 = (long long)M * DIM / 4;
        split_hi<<<(unsigned)((n4 + 255) / 256), 256>>>((const float4*)X, xh, n4);
    }
    splitT_kernel<<<dim3(DIM3 / 32, DIM / 32, 1), 256>>>(W_qkv, DIM3, 0, wqh, wql, DIM, 0);
    splitT_kernel<<<dim3(DIM / 32, DIM / 32, 1), 256>>>(W_out, DIM, 0, woh, wol, DIM, 0);

    // 1) QKV = X @ Wqkv^T + b  -> f32 + fp16 hi/lo
    gemm_mma<<<dim3(DIM3 / 64, M / 128, 1), 256, GEMM_SMEM>>>(
        xh, 0, DIM, wqh, wql, 0, DIM,
        qkv, qkvh, qkvl, 0, DIM3, b_qkv, nullptr, 0, 1.0f, DIM);

    // V^T hi/lo
    splitT_kernel<<<dim3(DIM / 32, SEQ / 32, BATCH), 256>>>(
        qkv + 2 * DIM, DIM3, (long long)SEQ * DIM3, vth, vtl, SEQ, (long long)DIM * SEQ);

    // 2) scores = mask ? NEG : (Q K^T)/32  -> f32
    gemm_mma<<<dim3(SEQ / 64, SEQ / 128, BATCH), 256, GEMM_SMEM>>>(
        qkvh, (long long)SEQ * DIM3, DIM3,
        qkvh + DIM, qkvl + DIM, (long long)SEQ * DIM3, DIM3,
        scores, nullptr, nullptr, (long long)SEQ * SEQ, SEQ,
        nullptr, mask, (long long)SEQ * SEQ, scale, DIM);

    // 3) softmax f32 -> fp16
    softmax_h<<<BATCH * SEQ, 256>>>(scores, sh, SEQ);

    // 4) ctx = attn @ V  -> fp16 hi only
    gemm_mma<<<dim3(DIM / 64, SEQ / 128, BATCH), 256, GEMM_SMEM>>>(
        sh, (long long)SEQ * SEQ, SEQ,
        vth, vtl, (long long)DIM * SEQ, SEQ,
        nullptr, ch, nullptr, (long long)SEQ * DIM, DIM,
        nullptr, nullptr, 0, 1.0f, SEQ);

    // 5) out = ctx @ Wout^T + b
    gemm_mma<<<dim3(DIM / 64, M / 128, 1), 256, GEMM_SMEM>>>(
        ch, 0, DIM, woh, wol, 0, DIM,
        out, nullptr, nullptr, 0, DIM, b_out, nullptr, 0, 1.0f, DIM);
}

// round 13
// speedup vs baseline: 2.2939x; 1.4198x over previous
#include <cuda_runtime.h>
#include <cuda_fp16.h>
#include <math_constants.h>
#include <cstdint>

#define BATCH 4
#define SEQ   2048
#define DIM   1024
#define DIM3  3072
#define NEGV  (-1e20f)

// ---------------- scratch (device globals; no allocation) ----------------
__device__ float g_scores[(size_t)BATCH * SEQ * SEQ];          // 64 MB

__device__ __half g_xh [(size_t)BATCH * SEQ * DIM];
__device__ __half g_xl [(size_t)BATCH * SEQ * DIM];
__device__ __half g_qkh[(size_t)BATCH * SEQ * 2 * DIM];        // Q,K hi  [8192][2048]
__device__ __half g_qkl[(size_t)BATCH * SEQ * 2 * DIM];        // Q,K lo
__device__ __half g_wqh[(size_t)DIM3 * DIM];
__device__ __half g_wql[(size_t)DIM3 * DIM];
__device__ __half g_vth[(size_t)BATCH * DIM * SEQ];            // V^T hi [b][d][s]
__device__ __half g_vtl[(size_t)BATCH * DIM * SEQ];
__device__ __half g_sh [(size_t)BATCH * SEQ * SEQ];
__device__ __half g_ch [(size_t)BATCH * SEQ * DIM];
__device__ __half g_woh[(size_t)DIM * DIM];
__device__ __half g_wol[(size_t)DIM * DIM];

// ---------------- helpers ----------------
__device__ __forceinline__ uint32_t smem_u32(const void* p) {
    uint32_t a;
    asm("{ .reg .u64 t; cvta.to.shared.u64 t, %1; cvt.u32.u64 %0, t; }" : "=r"(a) : "l"(p));
    return a;
}
__device__ __forceinline__ uint32_t sw128(uint32_t o) { return o ^ ((o >> 3) & 0x70); }

#define CP_ASYNC16(dst, src) \
    asm volatile("cp.async.cg.shared.global [%0], [%1], 16;" :: "r"(dst), "l"(src))
#define CP_COMMIT() asm volatile("cp.async.commit_group;")
#define CP_WAIT1()  asm volatile("cp.async.wait_group 1;")
#define CP_WAIT0()  asm volatile("cp.async.wait_group 0;")

#define LDSM4(r0, r1, r2, r3, a) \
    asm volatile("ldmatrix.sync.aligned.m8n8.x4.shared.b16 {%0,%1,%2,%3}, [%4];" \
        : "=r"(r0), "=r"(r1), "=r"(r2), "=r"(r3) : "r"(a))

// fp32-accumulator HMMA: main (hi) pass
#define MMA16816F(c, a, b) \
    asm volatile("mma.sync.aligned.m16n8k16.row.col.f32.f16.f16.f32 " \
        "{%0,%1,%2,%3}, {%4,%5,%6,%7}, {%8,%9}, {%0,%1,%2,%3};" \
        : "+f"((c)[0]), "+f"((c)[1]), "+f"((c)[2]), "+f"((c)[3]) \
        : "r"((a)[0]), "r"((a)[1]), "r"((a)[2]), "r"((a)[3]), "r"((b)[0]), "r"((b)[1]))

// fp16-accumulator HMMA: lo-correction pass (flushed once in epilogue)
#define MMA16816H(c, a, b) \
    asm volatile("mma.sync.aligned.m16n8k16.row.col.f16.f16.f16.f16 " \
        "{%0,%1}, {%2,%3,%4,%5}, {%6,%7}, {%0,%1};" \
        : "+r"((c)[0]), "+r"((c)[1]) \
        : "r"((a)[0]), "r"((a)[1]), "r"((a)[2]), "r"((a)[3]), "r"((b)[0]), "r"((b)[1]))

// ---------------- GEMM: C[m,n] = sum_k A[m,k]*B[n,k] (K-major both) ----------------
// CTA tile 128x64, BK=64, 8 warps (4 M x 2 N), warp tile 32x32, 2 CTAs/SM.
// (R9 mainloop: cp.async.wait_group + __syncthreads convoy — measured best.)
#define OFF_A  0
#define OFF_BH 16384
#define OFF_BL 24576
#define STG    32768
#define GEMM_SMEM (3 * STG)   // 96 KB

__device__ __forceinline__ void load_stage(
    uint32_t sbase,
    const __half* __restrict__ Ah, int lda,
    const __half* __restrict__ Bh, const __half* __restrict__ Bl, int ldb,
    int k0, int tid)
{
#pragma unroll
    for (int it = 0; it < 4; it++) {           // A: 128 rows x 64 cols
        int idx = tid + it * 256;
        int row = idx >> 3, ch = idx & 7;
        uint32_t d = sw128((uint32_t)row * 128 + ch * 16);
        CP_ASYNC16(sbase + OFF_A + d, Ah + (size_t)row * lda + k0 + ch * 8);
    }
#pragma unroll
    for (int it = 0; it < 2; it++) {           // B hi/lo: 64 rows x 64 cols each
        int idx = tid + it * 256;
        int row = idx >> 3, ch = idx & 7;
        uint32_t d = sw128((uint32_t)row * 128 + ch * 16);
        size_t eb = (size_t)row * ldb + k0 + ch * 8;
        CP_ASYNC16(sbase + OFF_BH + d, Bh + eb);
        CP_ASYNC16(sbase + OFF_BL + d, Bl + eb);
    }
    CP_COMMIT();
}

__global__ __launch_bounds__(256, 2) void gemm_mma(
    const __half* __restrict__ Ah, long long sA, int lda,
    const __half* __restrict__ Bh, const __half* __restrict__ Bl, long long sB, int ldb,
    float* __restrict__ Cf, __half* __restrict__ Chi, __half* __restrict__ Clo,
    long long sC, int ldc,
    const float* __restrict__ bias, int bias_rows,
    const int* __restrict__ mask, long long sM, float scale,
    int K)
{
    extern __shared__ char smem[];
    uint32_t sb = smem_u32(smem);
    int tid = threadIdx.x, w = tid >> 5, l = tid & 31;
    int wm = (w >> 1) * 32, wn = (w & 1) * 32;   // 4 M-warps x 2 N-warps
    int b = blockIdx.z;
    Ah += (size_t)b * sA;
    Bh += (size_t)b * sB; Bl += (size_t)b * sB;
    if (Cf)  Cf  += (size_t)b * sC;
    if (Chi) Chi += (size_t)b * sC;
    if (Clo) Clo += (size_t)b * sC;
    if (mask) mask += (size_t)b * sM;
    int row0 = blockIdx.y * 128, col0 = blockIdx.x * 64;

    const __half* Ahr = Ah + (size_t)row0 * lda;
    const __half* Bhr = Bh + (size_t)col0 * ldb;
    const __half* Blr = Bl + (size_t)col0 * ldb;

    uint32_t aoffb[2], boffb[2];
#pragma unroll
    for (int mt = 0; mt < 2; mt++)
        aoffb[mt] = sw128((uint32_t)(wm + mt * 16 + (l & 15)) * 128 + (l >> 4) * 16);
#pragma unroll
    for (int g = 0; g < 2; g++)
        boffb[g] = sw128((uint32_t)(wn + g * 16 + (l & 15)) * 128 + (l >> 4) * 16);

    float acc[2][4][4];
    uint32_t acc16[2][4][2];
#pragma unroll
    for (int mt = 0; mt < 2; mt++)
#pragma unroll
        for (int nt = 0; nt < 4; nt++) {
#pragma unroll
            for (int r = 0; r < 4; r++) acc[mt][nt][r] = 0.0f;
            acc16[mt][nt][0] = 0u; acc16[mt][nt][1] = 0u;
        }

    const int L = K >> 6;
    load_stage(sb + 0 * STG, Ahr, lda, Bhr, Blr, ldb, 0, tid);
    load_stage(sb + 1 * STG, Ahr, lda, Bhr, Blr, ldb, 64, tid);

    for (int i = 0; i < L; i++) {
        if (i == L - 1) { CP_WAIT0(); } else { CP_WAIT1(); }
        __syncthreads();
        if (i + 2 < L)
            load_stage(sb + ((i + 2) % 3) * STG, Ahr, lda, Bhr, Blr, ldb, (i + 2) * 64, tid);

        uint32_t base = sb + (i % 3) * STG;
#pragma unroll
        for (int ks = 0; ks < 4; ks++) {
            uint32_t kx = (uint32_t)ks * 32;
            uint32_t a[2][4], bb[4][2];
#pragma unroll
            for (int mt = 0; mt < 2; mt++)
                LDSM4(a[mt][0], a[mt][1], a[mt][2], a[mt][3], base + OFF_A + (aoffb[mt] ^ kx));
#pragma unroll
            for (int g = 0; g < 2; g++) {
                uint32_t q0, q1, q2, q3;
                LDSM4(q0, q1, q2, q3, base + OFF_BH + (boffb[g] ^ kx));
                bb[2 * g][0] = q0; bb[2 * g][1] = q2;
                bb[2 * g + 1][0] = q1; bb[2 * g + 1][1] = q3;
            }
#pragma unroll
            for (int mt = 0; mt < 2; mt++)
#pragma unroll
                for (int nt = 0; nt < 4; nt++)
                    MMA16816F(acc[mt][nt], a[mt], bb[nt]);
            // reload B-lo into same fragment regs (in-order issue: safe WAR)
#pragma unroll
            for (int g = 0; g < 2; g++) {
                uint32_t q0, q1, q2, q3;
                LDSM4(q0, q1, q2, q3, base + OFF_BL + (boffb[g] ^ kx));
                bb[2 * g][0] = q0; bb[2 * g][1] = q2;
                bb[2 * g + 1][0] = q1; bb[2 * g + 1][1] = q3;
            }
#pragma unroll
            for (int mt = 0; mt < 2; mt++)
#pragma unroll
                for (int nt = 0; nt < 4; nt++)
                    MMA16816H(acc16[mt][nt], a[mt], bb[nt]);
        }
    }

    // ---- epilogue: flush fp16 correction, then store ----
#pragma unroll
    for (int mt = 0; mt < 2; mt++) {
        int r0 = row0 + wm + mt * 16 + (l >> 2);
        int r1 = r0 + 8;
#pragma unroll
        for (int nt = 0; nt < 4; nt++) {
            float2 f01 = __half22float2(*(__half2*)&acc16[mt][nt][0]);
            float2 f23 = __half22float2(*(__half2*)&acc16[mt][nt][1]);
            float2 v0 = make_float2(acc[mt][nt][0] + f01.x, acc[mt][nt][1] + f01.y);
            float2 v1 = make_float2(acc[mt][nt][2] + f23.x, acc[mt][nt][3] + f23.y);

            int c = col0 + wn + nt * 8 + 2 * (l & 3);
            if (bias) {
                if (bias_rows) {
                    float b0 = __ldg(&bias[r0]), b1 = __ldg(&bias[r1]);
                    v0.x += b0; v0.y += b0; v1.x += b1; v1.y += b1;
                } else {
                    float2 bb2 = *(const float2*)(bias + c);
                    v0.x += bb2.x; v0.y += bb2.y; v1.x += bb2.x; v1.y += bb2.y;
                }
            }
            if (mask) {
                int2 m0 = *(const int2*)(mask + (size_t)r0 * ldc + c);
                int2 m1 = *(const int2*)(mask + (size_t)r1 * ldc + c);
                v0.x = m0.x ? NEGV : v0.x * scale;
                v0.y = m0.y ? NEGV : v0.y * scale;
                v1.x = m1.x ? NEGV : v1.x * scale;
                v1.y = m1.y ? NEGV : v1.y * scale;
            }
            if (Cf) {
                *(float2*)(Cf + (size_t)r0 * ldc + c) = v0;
                *(float2*)(Cf + (size_t)r1 * ldc + c) = v1;
            }
            if (Chi) {
                __half h0 = __float2half(v0.x), h1 = __float2half(v0.y);
                __half h2 = __float2half(v1.x), h3 = __float2half(v1.y);
                *(__half2*)(Chi + (size_t)r0 * ldc + c) = __halves2half2(h0, h1);
                *(__half2*)(Chi + (size_t)r1 * ldc + c) = __halves2half2(h2, h3);
                if (Clo) {
                    __half l0 = __float2half(v0.x - __half2float(h0));
                    __half l1 = __float2half(v0.y - __half2float(h1));
                    __half l2 = __float2half(v1.x - __half2float(h2));
                    __half l3 = __float2half(v1.y - __half2float(h3));
                    *(__half2*)(Clo + (size_t)r0 * ldc + c) = __halves2half2(l0, l1);
                    *(__half2*)(Clo + (size_t)r1 * ldc + c) = __halves2half2(l2, l3);
                }
            }
        }
    }
}

// ---------------- conversions ----------------
__global__ __launch_bounds__(256) void split_hl(
    const float4* __restrict__ in, __half* __restrict__ oh, __half* __restrict__ ol,
    long long n4)
{
    long long i = (long long)blockIdx.x * blockDim.x + threadIdx.x;
    if (i >= n4) return;
    float4 x = in[i];
    __half h0 = __float2half(x.x), h1 = __float2half(x.y);
    __half h2 = __float2half(x.z), h3 = __float2half(x.w);
    __half2 hp0 = __halves2half2(h0, h1), hp1 = __halves2half2(h2, h3);
    *(uint2*)(oh + i * 4) = make_uint2(*(uint32_t*)&hp0, *(uint32_t*)&hp1);
    __half l0 = __float2half(x.x - __half2float(h0));
    __half l1 = __float2half(x.y - __half2float(h1));
    __half l2 = __float2half(x.z - __half2float(h2));
    __half l3 = __float2half(x.w - __half2float(h3));
    __half2 lp0 = __halves2half2(l0, l1), lp1 = __halves2half2(l2, l3);
    *(uint2*)(ol + i * 4) = make_uint2(*(uint32_t*)&lp0, *(uint32_t*)&lp1);
}

__global__ __launch_bounds__(256) void splitT_kernel(
    const float* __restrict__ in, int ldin, long long sIn,
    __half* __restrict__ oh, __half* __restrict__ ol, int ldout, long long sOut)
{
    __shared__ float t[32][33];
    int b = blockIdx.z;
    in += (size_t)b * sIn; oh += (size_t)b * sOut; ol += (size_t)b * sOut;
    int c0 = blockIdx.x * 32, r0 = blockIdx.y * 32;
    int tx = threadIdx.x & 31, ty = threadIdx.x >> 5;
#pragma unroll
    for (int k = 0; k < 4; k++) {
        int r = r0 + ty + k * 8;
        t[ty + k * 8][tx] = in[(size_t)r * ldin + c0 + tx];
    }
    __syncthreads();
#pragma unroll
    for (int k = 0; k < 4; k++) {
        int c = c0 + ty + k * 8;
        float v = t[tx][ty + k * 8];
        __half h = __float2half(v);
        oh[(size_t)c * ldout + r0 + tx] = h;
        ol[(size_t)c * ldout + r0 + tx] = __float2half(v - __half2float(h));
    }
}

// ---------------- softmax: f32 scores -> fp16 attn ----------------
__global__ __launch_bounds__(256) void softmax_h(
    const float* __restrict__ sc, __half* __restrict__ sh, int n)
{
    __shared__ float buf[SEQ];
    __shared__ float red[256];
    const float* row = sc + (size_t)blockIdx.x * n;
    __half* oh = sh + (size_t)blockIdx.x * n;
    int tid = threadIdx.x;

    float m = -CUDART_INF_F;
    for (int i = tid; i < n; i += 256) { float x = row[i]; buf[i] = x; m = fmaxf(m, x); }
    red[tid] = m; __syncthreads();
    for (int s = 128; s > 0; s >>= 1) {
        if (tid < s) red[tid] = fmaxf(red[tid], red[tid + s]);
        __syncthreads();
    }
    m = red[0];
    __syncthreads();

    float sum = 0.0f;
    for (int i = tid; i < n; i += 256) {
        float e = __expf(buf[i] - m);
        buf[i] = e; sum += e;
    }
    red[tid] = sum; __syncthreads();
    for (int s = 128; s > 0; s >>= 1) {
        if (tid < s) red[tid] += red[tid + s];
        __syncthreads();
    }
    float inv = 1.0f / red[0];
    for (int i = tid; i < n; i += 256) oh[i] = __float2half(buf[i] * inv);
}

// ---------------- host ----------------
extern "C" void kernel_launch(void* const* d_in, const int* in_sizes, int n_in,
                              void* d_out, int out_size)
{
    const float* X     = (const float*)d_in[0];
    const int*   mask  = (const int*)d_in[1];
    const float* W_qkv = (const float*)d_in[2];
    const float* b_qkv = (const float*)d_in[3];
    const float* W_out = (const float*)d_in[4];
    const float* b_out = (const float*)d_in[5];
    float*       out   = (float*)d_out;

    float *scores;
    __half *xh, *xl, *qkh, *qkl, *wqh, *wql, *vth, *vtl, *sh, *ch, *woh, *wol;
    cudaGetSymbolAddress((void**)&scores, g_scores);
    cudaGetSymbolAddress((void**)&xh, g_xh);   cudaGetSymbolAddress((void**)&xl, g_xl);
    cudaGetSymbolAddress((void**)&qkh, g_qkh); cudaGetSymbolAddress((void**)&qkl, g_qkl);
    cudaGetSymbolAddress((void**)&wqh, g_wqh); cudaGetSymbolAddress((void**)&wql, g_wql);
    cudaGetSymbolAddress((void**)&vth, g_vth); cudaGetSymbolAddress((void**)&vtl, g_vtl);
    cudaGetSymbolAddress((void**)&sh, g_sh);
    cudaGetSymbolAddress((void**)&ch, g_ch);
    cudaGetSymbolAddress((void**)&woh, g_woh); cudaGetSymbolAddress((void**)&wol, g_wol);

    cudaFuncSetAttribute(gemm_mma, cudaFuncAttributeMaxDynamicSharedMemorySize, GEMM_SMEM);

    const int M = BATCH * SEQ;            // 8192
    const int QK = 2 * DIM;               // 2048
    const float scale = 1.0f / 32.0f;

    {   // X -> hi/lo fp16
        long long n4 = (long long)M * DIM / 4;
        split_hl<<<(unsigned)((n4 + 255) / 256), 256>>>((const float4*)X, xh, xl, n4);
    }
    splitT_kernel<<<dim3(DIM3 / 32, DIM / 32, 1), 256>>>(W_qkv, DIM3, 0, wqh, wql, DIM, 0);
    splitT_kernel<<<dim3(DIM / 32, DIM / 32, 1), 256>>>(W_out, DIM, 0, woh, wol, DIM, 0);

    // 1a) QK = X @ Wqk^T + b_qkv[0:2048]  -> fp16 hi/lo only  [8192][2048]
    gemm_mma<<<dim3(QK / 64, M / 128, 1), 256, GEMM_SMEM>>>(
        xh, 0, DIM, wqh, wql, 0, DIM,
        nullptr, qkh, qkl, 0, QK, b_qkv, 0, nullptr, 0, 1.0f, DIM);

    // 1b) V^T[d][s] = sum_k Wv^T[d,k] X[s,k] + b_qkv[2048+d]  -> vth/vtl per batch
    gemm_mma<<<dim3(SEQ / 64, DIM / 128, BATCH), 256, GEMM_SMEM>>>(
        wqh + (size_t)QK * DIM, 0, DIM,
        xh, xl, (long long)SEQ * DIM, DIM,
        nullptr, vth, vtl, (long long)DIM * SEQ, SEQ,
        b_qkv + QK, 1, nullptr, 0, 1.0f, DIM);

    // 2) scores = mask ? NEG : (Q K^T)/32  -> f32
    gemm_mma<<<dim3(SEQ / 64, SEQ / 128, BATCH), 256, GEMM_SMEM>>>(
        qkh, (long long)SEQ * QK, QK,
        qkh + DIM, qkl + DIM, (long long)SEQ * QK, QK,
        scores, nullptr, nullptr, (long long)SEQ * SEQ, SEQ,
        nullptr, 0, mask, (long long)SEQ * SEQ, scale, DIM);

    // 3) softmax f32 -> fp16
    softmax_h<<<BATCH * SEQ, 256>>>(scores, sh, SEQ);

    // 4) ctx = attn @ V  (B = V^T hi/lo)  -> fp16 hi only
    gemm_mma<<<dim3(DIM / 64, SEQ / 128, BATCH), 256, GEMM_SMEM>>>(
        sh, (long long)SEQ * SEQ, SEQ,
        vth, vtl, (long long)DIM * SEQ, SEQ,
        nullptr, ch, nullptr, (long long)SEQ * DIM, DIM,
        nullptr, 0, nullptr, 0, 1.0f, SEQ);

    // 5) out = ctx @ Wout^T + b_out  -> f32
    gemm_mma<<<dim3(DIM / 64, M / 128, 1), 256, GEMM_SMEM>>>(
        ch, 0, DIM, woh, wol, 0, DIM,
        out, nullptr, nullptr, 0, DIM, b_out, 0, nullptr, 0, 1.0f, DIM);
}

// round 14
// speedup vs baseline: 2.8047x; 1.2227x over previous
#include <cuda_runtime.h>
#include <cuda_fp16.h>
#include <math_constants.h>
#include <cstdint>

#define BATCH 4
#define SEQ   2048
#define DIM   1024
#define DIM3  3072
#define NEGV  (-1e20f)

// ---------------- scratch (device globals; no allocation) ----------------
__device__ float g_scores[(size_t)BATCH * SEQ * SEQ];          // 64 MB

__device__ __half g_xh [(size_t)BATCH * SEQ * DIM];
__device__ __half g_xl [(size_t)BATCH * SEQ * DIM];
__device__ __half g_qkh[(size_t)BATCH * SEQ * 2 * DIM];        // Q,K hi  [8192][2048]
__device__ __half g_wqh[(size_t)DIM3 * DIM];
__device__ __half g_wql[(size_t)DIM3 * DIM];
__device__ __half g_vth[(size_t)BATCH * DIM * SEQ];            // V^T hi [b][d][s]
__device__ __half g_sh [(size_t)BATCH * SEQ * SEQ];
__device__ __half g_ch [(size_t)BATCH * SEQ * DIM];
__device__ __half g_woh[(size_t)DIM * DIM];
__device__ __half g_wol[(size_t)DIM * DIM];

// ---------------- helpers ----------------
__device__ __forceinline__ uint32_t smem_u32(const void* p) {
    uint32_t a;
    asm("{ .reg .u64 t; cvta.to.shared.u64 t, %1; cvt.u32.u64 %0, t; }" : "=r"(a) : "l"(p));
    return a;
}
__device__ __forceinline__ uint32_t sw128(uint32_t o) { return o ^ ((o >> 3) & 0x70); }

#define CP_ASYNC16(dst, src) \
    asm volatile("cp.async.cg.shared.global [%0], [%1], 16;" :: "r"(dst), "l"(src))
#define CP_COMMIT() asm volatile("cp.async.commit_group;")
#define CP_WAIT1()  asm volatile("cp.async.wait_group 1;")
#define CP_WAIT0()  asm volatile("cp.async.wait_group 0;")

#define LDSM4(r0, r1, r2, r3, a) \
    asm volatile("ldmatrix.sync.aligned.m8n8.x4.shared.b16 {%0,%1,%2,%3}, [%4];" \
        : "=r"(r0), "=r"(r1), "=r"(r2), "=r"(r3) : "r"(a))

// fp32-accumulator HMMA: main (hi) pass
#define MMA16816F(c, a, b) \
    asm volatile("mma.sync.aligned.m16n8k16.row.col.f32.f16.f16.f32 " \
        "{%0,%1,%2,%3}, {%4,%5,%6,%7}, {%8,%9}, {%0,%1,%2,%3};" \
        : "+f"((c)[0]), "+f"((c)[1]), "+f"((c)[2]), "+f"((c)[3]) \
        : "r"((a)[0]), "r"((a)[1]), "r"((a)[2]), "r"((a)[3]), "r"((b)[0]), "r"((b)[1]))

// fp16-accumulator HMMA: lo-correction pass (flushed once in epilogue)
#define MMA16816H(c, a, b) \
    asm volatile("mma.sync.aligned.m16n8k16.row.col.f16.f16.f16.f16 " \
        "{%0,%1}, {%2,%3,%4,%5}, {%6,%7}, {%0,%1};" \
        : "+r"((c)[0]), "+r"((c)[1]) \
        : "r"((a)[0]), "r"((a)[1]), "r"((a)[2]), "r"((a)[3]), "r"((b)[0]), "r"((b)[1]))

// ---------------- GEMM: C[m,n] = sum_k A[m,k]*B[n,k] (K-major both) ----------------
// CTA tile 128x64, BK=64, 8 warps (4 M x 2 N), warp tile 32x32, 2 CTAs/SM.
// Bl == nullptr => single-pass (hi only): skip BL loads + H-pass MMAs.
#define OFF_A  0
#define OFF_BH 16384
#define OFF_BL 24576
#define STG    32768
#define GEMM_SMEM (3 * STG)   // 96 KB

__device__ __forceinline__ void load_stage(
    uint32_t sbase,
    const __half* __restrict__ Ah, int lda,
    const __half* __restrict__ Bh, const __half* __restrict__ Bl, int ldb,
    int k0, int tid)
{
#pragma unroll
    for (int it = 0; it < 4; it++) {           // A: 128 rows x 64 cols
        int idx = tid + it * 256;
        int row = idx >> 3, ch = idx & 7;
        uint32_t d = sw128((uint32_t)row * 128 + ch * 16);
        CP_ASYNC16(sbase + OFF_A + d, Ah + (size_t)row * lda + k0 + ch * 8);
    }
#pragma unroll
    for (int it = 0; it < 2; it++) {           // B hi (and lo if present): 64 rows x 64
        int idx = tid + it * 256;
        int row = idx >> 3, ch = idx & 7;
        uint32_t d = sw128((uint32_t)row * 128 + ch * 16);
        size_t eb = (size_t)row * ldb + k0 + ch * 8;
        CP_ASYNC16(sbase + OFF_BH + d, Bh + eb);
        if (Bl) CP_ASYNC16(sbase + OFF_BL + d, Bl + eb);
    }
    CP_COMMIT();
}

__global__ __launch_bounds__(256, 2) void gemm_mma(
    const __half* __restrict__ Ah, long long sA, int lda,
    const __half* __restrict__ Bh, const __half* __restrict__ Bl, long long sB, int ldb,
    float* __restrict__ Cf, __half* __restrict__ Chi, __half* __restrict__ Clo,
    long long sC, int ldc,
    const float* __restrict__ bias, int bias_rows,
    const int* __restrict__ mask, long long sM, float scale,
    int K)
{
    extern __shared__ char smem[];
    uint32_t sb = smem_u32(smem);
    int tid = threadIdx.x, w = tid >> 5, l = tid & 31;
    int wm = (w >> 1) * 32, wn = (w & 1) * 32;   // 4 M-warps x 2 N-warps
    int b = blockIdx.z;
    Ah += (size_t)b * sA;
    Bh += (size_t)b * sB;
    if (Bl) Bl += (size_t)b * sB;
    if (Cf)  Cf  += (size_t)b * sC;
    if (Chi) Chi += (size_t)b * sC;
    if (Clo) Clo += (size_t)b * sC;
    if (mask) mask += (size_t)b * sM;
    int row0 = blockIdx.y * 128, col0 = blockIdx.x * 64;

    const __half* Ahr = Ah + (size_t)row0 * lda;
    const __half* Bhr = Bh + (size_t)col0 * ldb;
    const __half* Blr = Bl ? (Bl + (size_t)col0 * ldb) : (const __half*)0;

    uint32_t aoffb[2], boffb[2];
#pragma unroll
    for (int mt = 0; mt < 2; mt++)
        aoffb[mt] = sw128((uint32_t)(wm + mt * 16 + (l & 15)) * 128 + (l >> 4) * 16);
#pragma unroll
    for (int g = 0; g < 2; g++)
        boffb[g] = sw128((uint32_t)(wn + g * 16 + (l & 15)) * 128 + (l >> 4) * 16);

    float acc[2][4][4];
    uint32_t acc16[2][4][2];
#pragma unroll
    for (int mt = 0; mt < 2; mt++)
#pragma unroll
        for (int nt = 0; nt < 4; nt++) {
#pragma unroll
            for (int r = 0; r < 4; r++) acc[mt][nt][r] = 0.0f;
            acc16[mt][nt][0] = 0u; acc16[mt][nt][1] = 0u;
        }

    const int L = K >> 6;
    load_stage(sb + 0 * STG, Ahr, lda, Bhr, Blr, ldb, 0, tid);
    load_stage(sb + 1 * STG, Ahr, lda, Bhr, Blr, ldb, 64, tid);

    for (int i = 0; i < L; i++) {
        if (i == L - 1) { CP_WAIT0(); } else { CP_WAIT1(); }
        __syncthreads();
        if (i + 2 < L)
            load_stage(sb + ((i + 2) % 3) * STG, Ahr, lda, Bhr, Blr, ldb, (i + 2) * 64, tid);

        uint32_t base = sb + (i % 3) * STG;
#pragma unroll
        for (int ks = 0; ks < 4; ks++) {
            uint32_t kx = (uint32_t)ks * 32;
            uint32_t a[2][4], bb[4][2];
#pragma unroll
            for (int mt = 0; mt < 2; mt++)
                LDSM4(a[mt][0], a[mt][1], a[mt][2], a[mt][3], base + OFF_A + (aoffb[mt] ^ kx));
#pragma unroll
            for (int g = 0; g < 2; g++) {
                uint32_t q0, q1, q2, q3;
                LDSM4(q0, q1, q2, q3, base + OFF_BH + (boffb[g] ^ kx));
                bb[2 * g][0] = q0; bb[2 * g][1] = q2;
                bb[2 * g + 1][0] = q1; bb[2 * g + 1][1] = q3;
            }
#pragma unroll
            for (int mt = 0; mt < 2; mt++)
#pragma unroll
                for (int nt = 0; nt < 4; nt++)
                    MMA16816F(acc[mt][nt], a[mt], bb[nt]);
            if (Bl) {
                // reload B-lo into same fragment regs (in-order issue: safe WAR)
#pragma unroll
                for (int g = 0; g < 2; g++) {
                    uint32_t q0, q1, q2, q3;
                    LDSM4(q0, q1, q2, q3, base + OFF_BL + (boffb[g] ^ kx));
                    bb[2 * g][0] = q0; bb[2 * g][1] = q2;
                    bb[2 * g + 1][0] = q1; bb[2 * g + 1][1] = q3;
                }
#pragma unroll
                for (int mt = 0; mt < 2; mt++)
#pragma unroll
                    for (int nt = 0; nt < 4; nt++)
                        MMA16816H(acc16[mt][nt], a[mt], bb[nt]);
            }
        }
    }

    // ---- epilogue: flush fp16 correction (zero if single-pass), then store ----
#pragma unroll
    for (int mt = 0; mt < 2; mt++) {
        int r0 = row0 + wm + mt * 16 + (l >> 2);
        int r1 = r0 + 8;
#pragma unroll
        for (int nt = 0; nt < 4; nt++) {
            float2 f01 = __half22float2(*(__half2*)&acc16[mt][nt][0]);
            float2 f23 = __half22float2(*(__half2*)&acc16[mt][nt][1]);
            float2 v0 = make_float2(acc[mt][nt][0] + f01.x, acc[mt][nt][1] + f01.y);
            float2 v1 = make_float2(acc[mt][nt][2] + f23.x, acc[mt][nt][3] + f23.y);

            int c = col0 + wn + nt * 8 + 2 * (l & 3);
            if (bias) {
                if (bias_rows) {
                    float b0 = __ldg(&bias[r0]), b1 = __ldg(&bias[r1]);
                    v0.x += b0; v0.y += b0; v1.x += b1; v1.y += b1;
                } else {
                    float2 bb2 = *(const float2*)(bias + c);
                    v0.x += bb2.x; v0.y += bb2.y; v1.x += bb2.x; v1.y += bb2.y;
                }
            }
            if (mask) {
                int2 m0 = *(const int2*)(mask + (size_t)r0 * ldc + c);
                int2 m1 = *(const int2*)(mask + (size_t)r1 * ldc + c);
                v0.x = m0.x ? NEGV : v0.x * scale;
                v0.y = m0.y ? NEGV : v0.y * scale;
                v1.x = m1.x ? NEGV : v1.x * scale;
                v1.y = m1.y ? NEGV : v1.y * scale;
            }
            if (Cf) {
                *(float2*)(Cf + (size_t)r0 * ldc + c) = v0;
                *(float2*)(Cf + (size_t)r1 * ldc + c) = v1;
            }
            if (Chi) {
                __half h0 = __float2half(v0.x), h1 = __float2half(v0.y);
                __half h2 = __float2half(v1.x), h3 = __float2half(v1.y);
                *(__half2*)(Chi + (size_t)r0 * ldc + c) = __halves2half2(h0, h1);
                *(__half2*)(Chi + (size_t)r1 * ldc + c) = __halves2half2(h2, h3);
                if (Clo) {
                    __half l0 = __float2half(v0.x - __half2float(h0));
                    __half l1 = __float2half(v0.y - __half2float(h1));
                    __half l2 = __float2half(v1.x - __half2float(h2));
                    __half l3 = __float2half(v1.y - __half2float(h3));
                    *(__half2*)(Clo + (size_t)r0 * ldc + c) = __halves2half2(l0, l1);
                    *(__half2*)(Clo + (size_t)r1 * ldc + c) = __halves2half2(l2, l3);
                }
            }
        }
    }
}

// ---------------- conversions ----------------
__global__ __launch_bounds__(256) void split_hl(
    const float4* __restrict__ in, __half* __restrict__ oh, __half* __restrict__ ol,
    long long n4)
{
    long long i = (long long)blockIdx.x * blockDim.x + threadIdx.x;
    if (i >= n4) return;
    float4 x = in[i];
    __half h0 = __float2half(x.x), h1 = __float2half(x.y);
    __half h2 = __float2half(x.z), h3 = __float2half(x.w);
    __half2 hp0 = __halves2half2(h0, h1), hp1 = __halves2half2(h2, h3);
    *(uint2*)(oh + i * 4) = make_uint2(*(uint32_t*)&hp0, *(uint32_t*)&hp1);
    __half l0 = __float2half(x.x - __half2float(h0));
    __half l1 = __float2half(x.y - __half2float(h1));
    __half l2 = __float2half(x.z - __half2float(h2));
    __half l3 = __float2half(x.w - __half2float(h3));
    __half2 lp0 = __halves2half2(l0, l1), lp1 = __halves2half2(l2, l3);
    *(uint2*)(ol + i * 4) = make_uint2(*(uint32_t*)&lp0, *(uint32_t*)&lp1);
}

__global__ __launch_bounds__(256) void splitT_kernel(
    const float* __restrict__ in, int ldin, long long sIn,
    __half* __restrict__ oh, __half* __restrict__ ol, int ldout, long long sOut)
{
    __shared__ float t[32][33];
    int b = blockIdx.z;
    in += (size_t)b * sIn; oh += (size_t)b * sOut; ol += (size_t)b * sOut;
    int c0 = blockIdx.x * 32, r0 = blockIdx.y * 32;
    int tx = threadIdx.x & 31, ty = threadIdx.x >> 5;
#pragma unroll
    for (int k = 0; k < 4; k++) {
        int r = r0 + ty + k * 8;
        t[ty + k * 8][tx] = in[(size_t)r * ldin + c0 + tx];
    }
    __syncthreads();
#pragma unroll
    for (int k = 0; k < 4; k++) {
        int c = c0 + ty + k * 8;
        float v = t[tx][ty + k * 8];
        __half h = __float2half(v);
        oh[(size_t)c * ldout + r0 + tx] = h;
        ol[(size_t)c * ldout + r0 + tx] = __float2half(v - __half2float(h));
    }
}

// ---------------- softmax: f32 scores -> fp16 attn ----------------
__global__ __launch_bounds__(256) void softmax_h(
    const float* __restrict__ sc, __half* __restrict__ sh, int n)
{
    __shared__ float buf[SEQ];
    __shared__ float red[256];
    const float* row = sc + (size_t)blockIdx.x * n;
    __half* oh = sh + (size_t)blockIdx.x * n;
    int tid = threadIdx.x;

    float m = -CUDART_INF_F;
    for (int i = tid; i < n; i += 256) { float x = row[i]; buf[i] = x; m = fmaxf(m, x); }
    red[tid] = m; __syncthreads();
    for (int s = 128; s > 0; s >>= 1) {
        if (tid < s) red[tid] = fmaxf(red[tid], red[tid + s]);
        __syncthreads();
    }
    m = red[0];
    __syncthreads();

    float sum = 0.0f;
    for (int i = tid; i < n; i += 256) {
        float e = __expf(buf[i] - m);
        buf[i] = e; sum += e;
    }
    red[tid] = sum; __syncthreads();
    for (int s = 128; s > 0; s >>= 1) {
        if (tid < s) red[tid] += red[tid + s];
        __syncthreads();
    }
    float inv = 1.0f / red[0];
    for (int i = tid; i < n; i += 256) oh[i] = __float2half(buf[i] * inv);
}

// ---------------- host ----------------
extern "C" void kernel_launch(void* const* d_in, const int* in_sizes, int n_in,
                              void* d_out, int out_size)
{
    const float* X     = (const float*)d_in[0];
    const int*   mask  = (const int*)d_in[1];
    const float* W_qkv = (const float*)d_in[2];
    const float* b_qkv = (const float*)d_in[3];
    const float* W_out = (const float*)d_in[4];
    const float* b_out = (const float*)d_in[5];
    float*       out   = (float*)d_out;

    float *scores;
    __half *xh, *xl, *qkh, *wqh, *wql, *vth, *sh, *ch, *woh, *wol;
    cudaGetSymbolAddress((void**)&scores, g_scores);
    cudaGetSymbolAddress((void**)&xh, g_xh);   cudaGetSymbolAddress((void**)&xl, g_xl);
    cudaGetSymbolAddress((void**)&qkh, g_qkh);
    cudaGetSymbolAddress((void**)&wqh, g_wqh); cudaGetSymbolAddress((void**)&wql, g_wql);
    cudaGetSymbolAddress((void**)&vth, g_vth);
    cudaGetSymbolAddress((void**)&sh, g_sh);
    cudaGetSymbolAddress((void**)&ch, g_ch);
    cudaGetSymbolAddress((void**)&woh, g_woh); cudaGetSymbolAddress((void**)&wol, g_wol);

    cudaFuncSetAttribute(gemm_mma, cudaFuncAttributeMaxDynamicSharedMemorySize, GEMM_SMEM);

    const int M = BATCH * SEQ;            // 8192
    const int QK = 2 * DIM;               // 2048
    const float scale = 1.0f / 32.0f;

    {   // X -> hi/lo fp16
        long long n4 = (long long)M * DIM / 4;
        split_hl<<<(unsigned)((n4 + 255) / 256), 256>>>((const float4*)X, xh, xl, n4);
    }
    splitT_kernel<<<dim3(DIM3 / 32, DIM / 32, 1), 256>>>(W_qkv, DIM3, 0, wqh, wql, DIM, 0);
    splitT_kernel<<<dim3(DIM / 32, DIM / 32, 1), 256>>>(W_out, DIM, 0, woh, wol, DIM, 0);

    // 1a) QK = X @ Wqk^T + b_qkv[0:2048]  -> fp16 hi only (2-pass compute)
    gemm_mma<<<dim3(QK / 64, M / 128, 1), 256, GEMM_SMEM>>>(
        xh, 0, DIM, wqh, wql, 0, DIM,
        nullptr, qkh, nullptr, 0, QK, b_qkv, 0, nullptr, 0, 1.0f, DIM);

    // 1b) V^T[d][s] = sum_k Wv^T[d,k] X[s,k] + b_qkv[2048+d] -> hi only (2-pass compute)
    gemm_mma<<<dim3(SEQ / 64, DIM / 128, BATCH), 256, GEMM_SMEM>>>(
        wqh + (size_t)QK * DIM, 0, DIM,
        xh, xl, (long long)SEQ * DIM, DIM,
        nullptr, vth, nullptr, (long long)DIM * SEQ, SEQ,
        b_qkv + QK, 1, nullptr, 0, 1.0f, DIM);

    // 2) scores = mask ? NEG : (Q K^T)/32  -> f32  (single-pass hi x hi)
    gemm_mma<<<dim3(SEQ / 64, SEQ / 128, BATCH), 256, GEMM_SMEM>>>(
        qkh, (long long)SEQ * QK, QK,
        qkh + DIM, nullptr, (long long)SEQ * QK, QK,
        scores, nullptr, nullptr, (long long)SEQ * SEQ, SEQ,
        nullptr, 0, mask, (long long)SEQ * SEQ, scale, DIM);

    // 3) softmax f32 -> fp16
    softmax_h<<<BATCH * SEQ, 256>>>(scores, sh, SEQ);

    // 4) ctx = attn @ V  (B = V^T hi)  -> fp16 hi  (single-pass)
    gemm_mma<<<dim3(DIM / 64, SEQ / 128, BATCH), 256, GEMM_SMEM>>>(
        sh, (long long)SEQ * SEQ, SEQ,
        vth, nullptr, (long long)DIM * SEQ, SEQ,
        nullptr, ch, nullptr, (long long)SEQ * DIM, DIM,
        nullptr, 0, nullptr, 0, 1.0f, SEQ);

    // 5) out = ctx @ Wout^T + b_out  -> f32  (2-pass compute)
    gemm_mma<<<dim3(DIM / 64, M / 128, 1), 256, GEMM_SMEM>>>(
        ch, 0, DIM, woh, wol, 0, DIM,
        out, nullptr, nullptr, 0, DIM, b_out, 0, nullptr, 0, 1.0f, DIM);
}

// round 16
// speedup vs baseline: 3.3263x; 1.1860x over previous
#include <cuda_runtime.h>
#include <cuda_fp16.h>
#include <math_constants.h>
#include <cstdint>

#define BATCH 4
#define SEQ   2048
#define DIM   1024
#define DIM3  3072
#define NEGV  (-1e20f)

// ---------------- scratch (device globals; no allocation) ----------------
__device__ float g_scores[(size_t)BATCH * SEQ * SEQ];          // 64 MB

__device__ __half g_xh [(size_t)BATCH * SEQ * DIM];
__device__ __half g_xl [(size_t)BATCH * SEQ * DIM];
__device__ __half g_qkh[(size_t)BATCH * SEQ * 2 * DIM];        // Q,K hi  [8192][2048]
__device__ __half g_wqh[(size_t)DIM3 * DIM];
__device__ __half g_wql[(size_t)DIM3 * DIM];
__device__ __half g_vth[(size_t)BATCH * DIM * SEQ];            // V^T hi [b][d][s]
__device__ __half g_sh [(size_t)BATCH * SEQ * SEQ];
__device__ __half g_ch [(size_t)BATCH * SEQ * DIM];
__device__ __half g_woh[(size_t)DIM * DIM];
__device__ __half g_wol[(size_t)DIM * DIM];

// ---------------- helpers ----------------
__device__ __forceinline__ uint32_t smem_u32(const void* p) {
    uint32_t a;
    asm("{ .reg .u64 t; cvta.to.shared.u64 t, %1; cvt.u32.u64 %0, t; }" : "=r"(a) : "l"(p));
    return a;
}
__device__ __forceinline__ uint32_t sw128(uint32_t o) { return o ^ ((o >> 3) & 0x70); }

#define CP_ASYNC16(dst, src) \
    asm volatile("cp.async.cg.shared.global [%0], [%1], 16;" :: "r"(dst), "l"(src))
#define CP_COMMIT() asm volatile("cp.async.commit_group;")
#define CP_WAIT1()  asm volatile("cp.async.wait_group 1;")
#define CP_WAIT0()  asm volatile("cp.async.wait_group 0;")

#define LDSM4(r0, r1, r2, r3, a) \
    asm volatile("ldmatrix.sync.aligned.m8n8.x4.shared.b16 {%0,%1,%2,%3}, [%4];" \
        : "=r"(r0), "=r"(r1), "=r"(r2), "=r"(r3) : "r"(a))

// fp32-accumulator HMMA: main (hi) pass
#define MMA16816F(c, a, b) \
    asm volatile("mma.sync.aligned.m16n8k16.row.col.f32.f16.f16.f32 " \
        "{%0,%1,%2,%3}, {%4,%5,%6,%7}, {%8,%9}, {%0,%1,%2,%3};" \
        : "+f"((c)[0]), "+f"((c)[1]), "+f"((c)[2]), "+f"((c)[3]) \
        : "r"((a)[0]), "r"((a)[1]), "r"((a)[2]), "r"((a)[3]), "r"((b)[0]), "r"((b)[1]))

// fp16-accumulator HMMA: lo-correction pass (flushed once in epilogue)
#define MMA16816H(c, a, b) \
    asm volatile("mma.sync.aligned.m16n8k16.row.col.f16.f16.f16.f16 " \
        "{%0,%1}, {%2,%3,%4,%5}, {%6,%7}, {%0,%1};" \
        : "+r"((c)[0]), "+r"((c)[1]) \
        : "r"((a)[0]), "r"((a)[1]), "r"((a)[2]), "r"((a)[3]), "r"((b)[0]), "r"((b)[1]))

// ---------------- GEMM: C[m,n] = sum_k A[m,k]*B[n,k] (K-major both) ----------------
// CTA tile 128x64, BK=64, 8 warps (4 M x 2 N), warp tile 32x32, 2 CTAs/SM.
// Bl == nullptr => single-pass (hi only): skip BL loads + H-pass MMAs.
#define OFF_A  0
#define OFF_BH 16384
#define OFF_BL 24576
#define STG    32768
#define GEMM_SMEM (3 * STG)   // 96 KB

__device__ __forceinline__ void load_stage(
    uint32_t sbase,
    const __half* __restrict__ Ah, int lda,
    const __half* __restrict__ Bh, const __half* __restrict__ Bl, int ldb,
    int k0, int tid)
{
#pragma unroll
    for (int it = 0; it < 4; it++) {           // A: 128 rows x 64 cols
        int idx = tid + it * 256;
        int row = idx >> 3, ch = idx & 7;
        uint32_t d = sw128((uint32_t)row * 128 + ch * 16);
        CP_ASYNC16(sbase + OFF_A + d, Ah + (size_t)row * lda + k0 + ch * 8);
    }
#pragma unroll
    for (int it = 0; it < 2; it++) {           // B hi (and lo if present): 64 rows x 64
        int idx = tid + it * 256;
        int row = idx >> 3, ch = idx & 7;
        uint32_t d = sw128((uint32_t)row * 128 + ch * 16);
        size_t eb = (size_t)row * ldb + k0 + ch * 8;
        CP_ASYNC16(sbase + OFF_BH + d, Bh + eb);
        if (Bl) CP_ASYNC16(sbase + OFF_BL + d, Bl + eb);
    }
    CP_COMMIT();
}

__global__ __launch_bounds__(256, 2) void gemm_mma(
    const __half* __restrict__ Ah, long long sA, int lda,
    const __half* __restrict__ Bh, const __half* __restrict__ Bl, long long sB, int ldb,
    float* __restrict__ Cf, __half* __restrict__ Chi, __half* __restrict__ Clo,
    long long sC, int ldc,
    const float* __restrict__ bias, int bias_rows,
    const int* __restrict__ mask, long long sM, float scale,
    int K)
{
    extern __shared__ char smem[];
    uint32_t sb = smem_u32(smem);
    int tid = threadIdx.x, w = tid >> 5, l = tid & 31;
    int wm = (w >> 1) * 32, wn = (w & 1) * 32;   // 4 M-warps x 2 N-warps
    int b = blockIdx.z;
    Ah += (size_t)b * sA;
    Bh += (size_t)b * sB;
    if (Bl) Bl += (size_t)b * sB;
    if (Cf)  Cf  += (size_t)b * sC;
    if (Chi) Chi += (size_t)b * sC;
    if (Clo) Clo += (size_t)b * sC;
    if (mask) mask += (size_t)b * sM;
    int row0 = blockIdx.y * 128, col0 = blockIdx.x * 64;

    const __half* Ahr = Ah + (size_t)row0 * lda;
    const __half* Bhr = Bh + (size_t)col0 * ldb;
    const __half* Blr = Bl ? (Bl + (size_t)col0 * ldb) : (const __half*)0;

    uint32_t aoffb[2], boffb[2];
#pragma unroll
    for (int mt = 0; mt < 2; mt++)
        aoffb[mt] = sw128((uint32_t)(wm + mt * 16 + (l & 15)) * 128 + (l >> 4) * 16);
#pragma unroll
    for (int g = 0; g < 2; g++)
        boffb[g] = sw128((uint32_t)(wn + g * 16 + (l & 15)) * 128 + (l >> 4) * 16);

    float acc[2][4][4];
    uint32_t acc16[2][4][2];
#pragma unroll
    for (int mt = 0; mt < 2; mt++)
#pragma unroll
        for (int nt = 0; nt < 4; nt++) {
#pragma unroll
            for (int r = 0; r < 4; r++) acc[mt][nt][r] = 0.0f;
            acc16[mt][nt][0] = 0u; acc16[mt][nt][1] = 0u;
        }

    const int L = K >> 6;
    load_stage(sb + 0 * STG, Ahr, lda, Bhr, Blr, ldb, 0, tid);
    load_stage(sb + 1 * STG, Ahr, lda, Bhr, Blr, ldb, 64, tid);

    for (int i = 0; i < L; i++) {
        if (i == L - 1) { CP_WAIT0(); } else { CP_WAIT1(); }
        __syncthreads();
        if (i + 2 < L)
            load_stage(sb + ((i + 2) % 3) * STG, Ahr, lda, Bhr, Blr, ldb, (i + 2) * 64, tid);

        uint32_t base = sb + (i % 3) * STG;
#pragma unroll
        for (int ks = 0; ks < 4; ks++) {
            uint32_t kx = (uint32_t)ks * 32;
            uint32_t a[2][4], bb[4][2];
#pragma unroll
            for (int mt = 0; mt < 2; mt++)
                LDSM4(a[mt][0], a[mt][1], a[mt][2], a[mt][3], base + OFF_A + (aoffb[mt] ^ kx));
#pragma unroll
            for (int g = 0; g < 2; g++) {
                uint32_t q0, q1, q2, q3;
                LDSM4(q0, q1, q2, q3, base + OFF_BH + (boffb[g] ^ kx));
                bb[2 * g][0] = q0; bb[2 * g][1] = q2;
                bb[2 * g + 1][0] = q1; bb[2 * g + 1][1] = q3;
            }
#pragma unroll
            for (int mt = 0; mt < 2; mt++)
#pragma unroll
                for (int nt = 0; nt < 4; nt++)
                    MMA16816F(acc[mt][nt], a[mt], bb[nt]);
            if (Bl) {
                // reload B-lo into same fragment regs (in-order issue: safe WAR)
#pragma unroll
                for (int g = 0; g < 2; g++) {
                    uint32_t q0, q1, q2, q3;
                    LDSM4(q0, q1, q2, q3, base + OFF_BL + (boffb[g] ^ kx));
                    bb[2 * g][0] = q0; bb[2 * g][1] = q2;
                    bb[2 * g + 1][0] = q1; bb[2 * g + 1][1] = q3;
                }
#pragma unroll
                for (int mt = 0; mt < 2; mt++)
#pragma unroll
                    for (int nt = 0; nt < 4; nt++)
                        MMA16816H(acc16[mt][nt], a[mt], bb[nt]);
            }
        }
    }

    // ---- epilogue: flush fp16 correction (zero if single-pass), then store ----
#pragma unroll
    for (int mt = 0; mt < 2; mt++) {
        int r0 = row0 + wm + mt * 16 + (l >> 2);
        int r1 = r0 + 8;
#pragma unroll
        for (int nt = 0; nt < 4; nt++) {
            float2 f01 = __half22float2(*(__half2*)&acc16[mt][nt][0]);
            float2 f23 = __half22float2(*(__half2*)&acc16[mt][nt][1]);
            float2 v0 = make_float2(acc[mt][nt][0] + f01.x, acc[mt][nt][1] + f01.y);
            float2 v1 = make_float2(acc[mt][nt][2] + f23.x, acc[mt][nt][3] + f23.y);

            int c = col0 + wn + nt * 8 + 2 * (l & 3);
            if (bias) {
                if (bias_rows) {
                    float b0 = __ldg(&bias[r0]), b1 = __ldg(&bias[r1]);
                    v0.x += b0; v0.y += b0; v1.x += b1; v1.y += b1;
                } else {
                    float2 bb2 = *(const float2*)(bias + c);
                    v0.x += bb2.x; v0.y += bb2.y; v1.x += bb2.x; v1.y += bb2.y;
                }
            }
            if (mask) {
                int2 m0 = *(const int2*)(mask + (size_t)r0 * ldc + c);
                int2 m1 = *(const int2*)(mask + (size_t)r1 * ldc + c);
                v0.x = m0.x ? NEGV : v0.x * scale;
                v0.y = m0.y ? NEGV : v0.y * scale;
                v1.x = m1.x ? NEGV : v1.x * scale;
                v1.y = m1.y ? NEGV : v1.y * scale;
            }
            if (Cf) {
                *(float2*)(Cf + (size_t)r0 * ldc + c) = v0;
                *(float2*)(Cf + (size_t)r1 * ldc + c) = v1;
            }
            if (Chi) {
                __half h0 = __float2half(v0.x), h1 = __float2half(v0.y);
                __half h2 = __float2half(v1.x), h3 = __float2half(v1.y);
                *(__half2*)(Chi + (size_t)r0 * ldc + c) = __halves2half2(h0, h1);
                *(__half2*)(Chi + (size_t)r1 * ldc + c) = __halves2half2(h2, h3);
                if (Clo) {
                    __half l0 = __float2half(v0.x - __half2float(h0));
                    __half l1 = __float2half(v0.y - __half2float(h1));
                    __half l2 = __float2half(v1.x - __half2float(h2));
                    __half l3 = __float2half(v1.y - __half2float(h3));
                    *(__half2*)(Clo + (size_t)r0 * ldc + c) = __halves2half2(l0, l1);
                    *(__half2*)(Clo + (size_t)r1 * ldc + c) = __halves2half2(l2, l3);
                }
            }
        }
    }
}

// ---------------- conversions ----------------
__global__ __launch_bounds__(256) void split_hl(
    const float4* __restrict__ in, __half* __restrict__ oh, __half* __restrict__ ol,
    long long n4)
{
    long long i = (long long)blockIdx.x * blockDim.x + threadIdx.x;
    if (i >= n4) return;
    float4 x = in[i];
    __half h0 = __float2half(x.x), h1 = __float2half(x.y);
    __half h2 = __float2half(x.z), h3 = __float2half(x.w);
    __half2 hp0 = __halves2half2(h0, h1), hp1 = __halves2half2(h2, h3);
    *(uint2*)(oh + i * 4) = make_uint2(*(uint32_t*)&hp0, *(uint32_t*)&hp1);
    __half l0 = __float2half(x.x - __half2float(h0));
    __half l1 = __float2half(x.y - __half2float(h1));
    __half l2 = __float2half(x.z - __half2float(h2));
    __half l3 = __float2half(x.w - __half2float(h3));
    __half2 lp0 = __halves2half2(l0, l1), lp1 = __halves2half2(l2, l3);
    *(uint2*)(ol + i * 4) = make_uint2(*(uint32_t*)&lp0, *(uint32_t*)&lp1);
}

__global__ __launch_bounds__(256) void splitT_kernel(
    const float* __restrict__ in, int ldin, long long sIn,
    __half* __restrict__ oh, __half* __restrict__ ol, int ldout, long long sOut)
{
    __shared__ float t[32][33];
    int b = blockIdx.z;
    in += (size_t)b * sIn; oh += (size_t)b * sOut; ol += (size_t)b * sOut;
    int c0 = blockIdx.x * 32, r0 = blockIdx.y * 32;
    int tx = threadIdx.x & 31, ty = threadIdx.x >> 5;
#pragma unroll
    for (int k = 0; k < 4; k++) {
        int r = r0 + ty + k * 8;
        t[ty + k * 8][tx] = in[(size_t)r * ldin + c0 + tx];
    }
    __syncthreads();
#pragma unroll
    for (int k = 0; k < 4; k++) {
        int c = c0 + ty + k * 8;
        float v = t[tx][ty + k * 8];
        __half h = __float2half(v);
        oh[(size_t)c * ldout + r0 + tx] = h;
        ol[(size_t)c * ldout + r0 + tx] = __float2half(v - __half2float(h));
    }
}

// ---------------- softmax: f32 scores -> fp16 attn ----------------
__global__ __launch_bounds__(256) void softmax_h(
    const float* __restrict__ sc, __half* __restrict__ sh, int n)
{
    __shared__ float buf[SEQ];
    __shared__ float red[256];
    const float* row = sc + (size_t)blockIdx.x * n;
    __half* oh = sh + (size_t)blockIdx.x * n;
    int tid = threadIdx.x;

    float m = -CUDART_INF_F;
    for (int i = tid; i < n; i += 256) { float x = row[i]; buf[i] = x; m = fmaxf(m, x); }
    red[tid] = m; __syncthreads();
    for (int s = 128; s > 0; s >>= 1) {
        if (tid < s) red[tid] = fmaxf(red[tid], red[tid + s]);
        __syncthreads();
    }
    m = red[0];
    __syncthreads();

    float sum = 0.0f;
    for (int i = tid; i < n; i += 256) {
        float e = __expf(buf[i] - m);
        buf[i] = e; sum += e;
    }
    red[tid] = sum; __syncthreads();
    for (int s = 128; s > 0; s >>= 1) {
        if (tid < s) red[tid] += red[tid + s];
        __syncthreads();
    }
    float inv = 1.0f / red[0];
    for (int i = tid; i < n; i += 256) oh[i] = __float2half(buf[i] * inv);
}

// ---------------- host ----------------
extern "C" void kernel_launch(void* const* d_in, const int* in_sizes, int n_in,
                              void* d_out, int out_size)
{
    const float* X     = (const float*)d_in[0];
    const int*   mask  = (const int*)d_in[1];
    const float* W_qkv = (const float*)d_in[2];
    const float* b_qkv = (const float*)d_in[3];
    const float* W_out = (const float*)d_in[4];
    const float* b_out = (const float*)d_in[5];
    float*       out   = (float*)d_out;

    float *scores;
    __half *xh, *xl, *qkh, *wqh, *wql, *vth, *sh, *ch, *woh, *wol;
    cudaGetSymbolAddress((void**)&scores, g_scores);
    cudaGetSymbolAddress((void**)&xh, g_xh);   cudaGetSymbolAddress((void**)&xl, g_xl);
    cudaGetSymbolAddress((void**)&qkh, g_qkh);
    cudaGetSymbolAddress((void**)&wqh, g_wqh); cudaGetSymbolAddress((void**)&wql, g_wql);
    cudaGetSymbolAddress((void**)&vth, g_vth);
    cudaGetSymbolAddress((void**)&sh, g_sh);
    cudaGetSymbolAddress((void**)&ch, g_ch);
    cudaGetSymbolAddress((void**)&woh, g_woh); cudaGetSymbolAddress((void**)&wol, g_wol);

    cudaFuncSetAttribute(gemm_mma, cudaFuncAttributeMaxDynamicSharedMemorySize, GEMM_SMEM);

    const int M = BATCH * SEQ;            // 8192
    const int QK = 2 * DIM;               // 2048
    const float scale = 1.0f / 32.0f;

    {   // X -> hi/lo fp16
        long long n4 = (long long)M * DIM / 4;
        split_hl<<<(unsigned)((n4 + 255) / 256), 256>>>((const float4*)X, xh, xl, n4);
    }
    splitT_kernel<<<dim3(DIM3 / 32, DIM / 32, 1), 256>>>(W_qkv, DIM3, 0, wqh, wql, DIM, 0);
    splitT_kernel<<<dim3(DIM / 32, DIM / 32, 1), 256>>>(W_out, DIM, 0, woh, wol, DIM, 0);

    // 1a) QK = X @ Wqk^T + b_qkv[0:2048]  -> fp16 hi (single-pass: output rounds
    //     to fp16 anyway, W-lo correction buys < storage quantization)
    gemm_mma<<<dim3(QK / 64, M / 128, 1), 256, GEMM_SMEM>>>(
        xh, 0, DIM, wqh, nullptr, 0, DIM,
        nullptr, qkh, nullptr, 0, QK, b_qkv, 0, nullptr, 0, 1.0f, DIM);

    // 1b) V^T[d][s] = sum_k Wv^T[d,k] X[s,k] + b_qkv[2048+d] -> fp16 hi (single-pass)
    gemm_mma<<<dim3(SEQ / 64, DIM / 128, BATCH), 256, GEMM_SMEM>>>(
        wqh + (size_t)QK * DIM, 0, DIM,
        xh, nullptr, (long long)SEQ * DIM, DIM,
        nullptr, vth, nullptr, (long long)DIM * SEQ, SEQ,
        b_qkv + QK, 1, nullptr, 0, 1.0f, DIM);

    // 2) scores = mask ? NEG : (Q K^T)/32  -> f32  (single-pass hi x hi)
    gemm_mma<<<dim3(SEQ / 64, SEQ / 128, BATCH), 256, GEMM_SMEM>>>(
        qkh, (long long)SEQ * QK, QK,
        qkh + DIM, nullptr, (long long)SEQ * QK, QK,
        scores, nullptr, nullptr, (long long)SEQ * SEQ, SEQ,
        nullptr, 0, mask, (long long)SEQ * SEQ, scale, DIM);

    // 3) softmax f32 -> fp16
    softmax_h<<<BATCH * SEQ, 256>>>(scores, sh, SEQ);

    // 4) ctx = attn @ V  (B = V^T hi)  -> fp16 hi  (single-pass)
    gemm_mma<<<dim3(DIM / 64, SEQ / 128, BATCH), 256, GEMM_SMEM>>>(
        sh, (long long)SEQ * SEQ, SEQ,
        vth, nullptr, (long long)DIM * SEQ, SEQ,
        nullptr, ch, nullptr, (long long)SEQ * DIM, DIM,
        nullptr, 0, nullptr, 0, 1.0f, SEQ);

    // 5) out = ctx @ Wout^T + b_out  -> f32  (keep 2-pass: f32 output, correction real)
    gemm_mma<<<dim3(DIM / 64, M / 128, 1), 256, GEMM_SMEM>>>(
        ch, 0, DIM, woh, wol, 0, DIM,
        out, nullptr, nullptr, 0, DIM, b_out, 0, nullptr, 0, 1.0f, DIM);
}